// round 1
// baseline (speedup 1.0000x reference)
#include <cuda_runtime.h>
#include <math.h>

#define B 4
#define H 16
#define S 2048
#define DM 1024
#define DH 64
#define SCALE 0.125f  // 1/sqrt(64)

// Scratch (device globals: no allocations allowed)
__device__ float g_q[(size_t)B*H*S*DH];      // [b][h][s][e]
__device__ float g_kt[(size_t)B*H*DH*S];     // [b][h][e][s]  (transposed K)
__device__ float g_v[(size_t)B*H*S*DH];      // [b][h][s][e]
__device__ float g_heads[(size_t)B*S*DM];    // [b][s][h*64+e] concat layout

// ---------------------------------------------------------------------------
// Kernel 1: QKV projection. grid(64 mtiles, 16 heads, 3 which), 256 threads.
// Computes a 128(s) x 64(e) tile of  x[b] @ W[h] + bias.
// which: 0=Q (natural), 1=K (written transposed), 2=V (natural).
// ---------------------------------------------------------------------------
__global__ __launch_bounds__(256) void qkv_kernel(
    const float* __restrict__ x,
    const float* __restrict__ Wq, const float* __restrict__ bq,
    const float* __restrict__ Wk, const float* __restrict__ bk,
    const float* __restrict__ Wv, const float* __restrict__ bv)
{
    __shared__ float xs[16][129];   // transposed x tile: [kk][r], pitch 129
    __shared__ float ws[16][68];    // w tile: [kk][e], pitch 68 (float4-aligned)

    const int mt    = blockIdx.x;
    const int h     = blockIdx.y;
    const int which = blockIdx.z;
    const float* Wp = (which == 0) ? Wq : (which == 1) ? Wk : Wv;
    const float* bp = (which == 0) ? bq : (which == 1) ? bk : bv;

    const int m0 = mt * 128;
    const int b  = m0 / S;
    const int s0 = m0 % S;
    const int tid = threadIdx.x;
    const int tx = tid & 15, ty = tid >> 4;

    float acc[8][4];
    #pragma unroll
    for (int i = 0; i < 8; i++)
        #pragma unroll
        for (int j = 0; j < 4; j++) acc[i][j] = 0.f;

    for (int k0 = 0; k0 < DM; k0 += 16) {
        // x tile 128x16 -> xs transposed
        {
            int c = tid & 3;
            int r = tid >> 2;
            #pragma unroll
            for (int p = 0; p < 2; p++) {
                int rr = r + p * 64;
                float4 v = *(const float4*)&x[(size_t)(m0 + rr) * DM + k0 + c * 4];
                xs[c*4+0][rr] = v.x; xs[c*4+1][rr] = v.y;
                xs[c*4+2][rr] = v.z; xs[c*4+3][rr] = v.w;
            }
        }
        // W tile 16x64
        {
            int c  = tid & 15;
            int kk = tid >> 4;
            float4 v = *(const float4*)&Wp[((size_t)h * DM + k0 + kk) * DH + c * 4];
            *(float4*)&ws[kk][c * 4] = v;
        }
        __syncthreads();
        #pragma unroll
        for (int kk = 0; kk < 16; kk++) {
            float a[8];
            #pragma unroll
            for (int i = 0; i < 8; i++) a[i] = xs[kk][ty * 8 + i];
            float4 bv4 = *(float4*)&ws[kk][tx * 4];
            float bb[4] = {bv4.x, bv4.y, bv4.z, bv4.w};
            #pragma unroll
            for (int i = 0; i < 8; i++)
                #pragma unroll
                for (int j = 0; j < 4; j++)
                    acc[i][j] += a[i] * bb[j];
        }
        __syncthreads();
    }

    float4 bias4 = *(const float4*)&bp[h * DH + tx * 4];
    float bb[4] = {bias4.x, bias4.y, bias4.z, bias4.w};

    if (which == 1) {
        // K: write transposed [b][h][e][s]
        #pragma unroll
        for (int j = 0; j < 4; j++) {
            int e = tx * 4 + j;
            size_t base = ((size_t)(b * H + h) * DH + e) * S + s0 + ty * 8;
            #pragma unroll
            for (int i = 0; i < 8; i++) g_kt[base + i] = acc[i][j] + bb[j];
        }
    } else {
        float* dst = (which == 0) ? g_q : g_v;
        #pragma unroll
        for (int i = 0; i < 8; i++) {
            float4 v = {acc[i][0] + bb[0], acc[i][1] + bb[1],
                        acc[i][2] + bb[2], acc[i][3] + bb[3]};
            *(float4*)&dst[((size_t)(b * H + h) * S + s0 + ty * 8 + i) * DH + tx * 4] = v;
        }
    }
}

// ---------------------------------------------------------------------------
// Kernel 2: attention, flash-style. grid(16 qtiles, 64 bh), 256 threads.
// Q tile 128 rows; loop over 32 KV tiles of 64. Register-resident running
// max/sum (replicated across the 16 lanes owning a row; shfl-reduced).
// ---------------------------------------------------------------------------
#define QS_P 129
#define KS_P 68
#define VS_P 68
#define PS_P 129
#define QS_OFF 0
#define KS_OFF (64 * QS_P)
#define VS_OFF (KS_OFF + 64 * KS_P)
#define PS_OFF (VS_OFF + 64 * VS_P)
#define ATT_SMEM_FLOATS (PS_OFF + 64 * PS_P)

__global__ __launch_bounds__(256, 2) void attn_kernel()
{
    extern __shared__ float sm[];
    float* qs = sm + QS_OFF;  // [d][r] 64 x pitch129
    float* ks = sm + KS_OFF;  // [d][c] 64 x pitch68
    float* vs = sm + VS_OFF;  // [c][e] 64 x pitch68
    float* ps = sm + PS_OFF;  // [c][r] 64 x pitch129

    const int qt = blockIdx.x;        // q tile (128 rows)
    const int bh = blockIdx.y;        // b*16 + h
    const int s0 = qt * 128;
    const int tid = threadIdx.x;
    const int tx = tid & 15, ty = tid >> 4;

    // Load + scale Q tile (128 s x 64 d) -> qs[d][r]
    {
        int c  = tid & 15;   // float4 chunk along d
        int r0 = tid >> 4;
        #pragma unroll
        for (int p = 0; p < 8; p++) {
            int r = r0 + p * 16;
            float4 v = *(const float4*)&g_q[((size_t)bh * S + s0 + r) * DH + c * 4];
            qs[(c*4+0)*QS_P + r] = v.x * SCALE;
            qs[(c*4+1)*QS_P + r] = v.y * SCALE;
            qs[(c*4+2)*QS_P + r] = v.z * SCALE;
            qs[(c*4+3)*QS_P + r] = v.w * SCALE;
        }
    }
    __syncthreads();

    float o[8][4];
    float m[8], l[8];
    #pragma unroll
    for (int i = 0; i < 8; i++) {
        m[i] = -INFINITY; l[i] = 0.f;
        #pragma unroll
        for (int j = 0; j < 4; j++) o[i][j] = 0.f;
    }

    for (int kt = 0; kt < S / 64; kt++) {
        // Load K tile from transposed global: [d][s] -> ks[d][c]
        {
            int c = tid & 15;
            int d0 = tid >> 4;
            #pragma unroll
            for (int p = 0; p < 4; p++) {
                int d = d0 + p * 16;
                float4 v = *(const float4*)&g_kt[((size_t)bh * DH + d) * S + kt * 64 + c * 4];
                *(float4*)&ks[d * KS_P + c * 4] = v;
            }
        }
        // Load V tile (natural [s][e]) -> vs[c][e]
        {
            int c = tid & 15;
            int r0 = tid >> 4;
            #pragma unroll
            for (int p = 0; p < 4; p++) {
                int r = r0 + p * 16;
                float4 v = *(const float4*)&g_v[((size_t)bh * S + kt * 64 + r) * DH + c * 4];
                *(float4*)&vs[r * VS_P + c * 4] = v;
            }
        }
        __syncthreads();

        // Scores: sc[8 rows][4 cols]
        float sc[8][4];
        #pragma unroll
        for (int i = 0; i < 8; i++)
            #pragma unroll
            for (int j = 0; j < 4; j++) sc[i][j] = 0.f;
        #pragma unroll 4
        for (int kk = 0; kk < 64; kk++) {
            float a[8];
            #pragma unroll
            for (int i = 0; i < 8; i++) a[i] = qs[kk * QS_P + ty * 8 + i];
            float4 bv4 = *(float4*)&ks[kk * KS_P + tx * 4];
            float bb[4] = {bv4.x, bv4.y, bv4.z, bv4.w};
            #pragma unroll
            for (int i = 0; i < 8; i++)
                #pragma unroll
                for (int j = 0; j < 4; j++)
                    sc[i][j] += a[i] * bb[j];
        }

        // Streaming softmax per row (16 lanes own each row; shfl over width 16)
        #pragma unroll
        for (int i = 0; i < 8; i++) {
            float mx = fmaxf(fmaxf(sc[i][0], sc[i][1]), fmaxf(sc[i][2], sc[i][3]));
            #pragma unroll
            for (int off = 8; off >= 1; off >>= 1)
                mx = fmaxf(mx, __shfl_xor_sync(0xffffffffu, mx, off));
            float mnew = fmaxf(m[i], mx);
            float f = __expf(m[i] - mnew);
            m[i] = mnew;
            float rs = 0.f;
            #pragma unroll
            for (int j = 0; j < 4; j++) {
                sc[i][j] = __expf(sc[i][j] - mnew);
                rs += sc[i][j];
            }
            #pragma unroll
            for (int off = 8; off >= 1; off >>= 1)
                rs += __shfl_xor_sync(0xffffffffu, rs, off);
            l[i] = l[i] * f + rs;
            #pragma unroll
            for (int j = 0; j < 4; j++) o[i][j] *= f;
            // write P transposed: ps[c][r]
            #pragma unroll
            for (int j = 0; j < 4; j++)
                ps[(tx * 4 + j) * PS_P + ty * 8 + i] = sc[i][j];
        }
        __syncthreads();

        // O += P @ V
        #pragma unroll 4
        for (int ck = 0; ck < 64; ck++) {
            float a[8];
            #pragma unroll
            for (int i = 0; i < 8; i++) a[i] = ps[ck * PS_P + ty * 8 + i];
            float4 bv4 = *(float4*)&vs[ck * VS_P + tx * 4];
            float bb[4] = {bv4.x, bv4.y, bv4.z, bv4.w};
            #pragma unroll
            for (int i = 0; i < 8; i++)
                #pragma unroll
                for (int j = 0; j < 4; j++)
                    o[i][j] += a[i] * bb[j];
        }
        __syncthreads();
    }

    // Finalize + write concat layout [b][s][h*64+e]
    const int b = bh >> 4;
    const int h = bh & 15;
    #pragma unroll
    for (int i = 0; i < 8; i++) {
        float inv = 1.f / l[i];
        float4 v = {o[i][0] * inv, o[i][1] * inv, o[i][2] * inv, o[i][3] * inv};
        *(float4*)&g_heads[((size_t)b * S + s0 + ty * 8 + i) * DM + h * DH + tx * 4] = v;
    }
}

// ---------------------------------------------------------------------------
// Kernel 3: output projection. grid(64 mtiles, 16 ntiles), 256 threads.
// out = heads[8192x1024] @ Wo[1024x1024] + bo
// ---------------------------------------------------------------------------
__global__ __launch_bounds__(256) void out_proj_kernel(
    const float* __restrict__ Wo, const float* __restrict__ bo,
    float* __restrict__ out)
{
    __shared__ float hs[16][129];
    __shared__ float ws[16][68];

    const int m0 = blockIdx.x * 128;
    const int n0 = blockIdx.y * 64;
    const int tid = threadIdx.x;
    const int tx = tid & 15, ty = tid >> 4;

    float acc[8][4];
    #pragma unroll
    for (int i = 0; i < 8; i++)
        #pragma unroll
        for (int j = 0; j < 4; j++) acc[i][j] = 0.f;

    for (int k0 = 0; k0 < DM; k0 += 16) {
        {
            int c = tid & 3;
            int r = tid >> 2;
            #pragma unroll
            for (int p = 0; p < 2; p++) {
                int rr = r + p * 64;
                float4 v = *(const float4*)&g_heads[(size_t)(m0 + rr) * DM + k0 + c * 4];
                hs[c*4+0][rr] = v.x; hs[c*4+1][rr] = v.y;
                hs[c*4+2][rr] = v.z; hs[c*4+3][rr] = v.w;
            }
        }
        {
            int c  = tid & 15;
            int kk = tid >> 4;
            float4 v = *(const float4*)&Wo[(size_t)(k0 + kk) * DM + n0 + c * 4];
            *(float4*)&ws[kk][c * 4] = v;
        }
        __syncthreads();
        #pragma unroll
        for (int kk = 0; kk < 16; kk++) {
            float a[8];
            #pragma unroll
            for (int i = 0; i < 8; i++) a[i] = hs[kk][ty * 8 + i];
            float4 bv4 = *(float4*)&ws[kk][tx * 4];
            float bb[4] = {bv4.x, bv4.y, bv4.z, bv4.w};
            #pragma unroll
            for (int i = 0; i < 8; i++)
                #pragma unroll
                for (int j = 0; j < 4; j++)
                    acc[i][j] += a[i] * bb[j];
        }
        __syncthreads();
    }

    float4 bias4 = *(const float4*)&bo[n0 + tx * 4];
    float bb[4] = {bias4.x, bias4.y, bias4.z, bias4.w};
    #pragma unroll
    for (int i = 0; i < 8; i++) {
        float4 v = {acc[i][0] + bb[0], acc[i][1] + bb[1],
                    acc[i][2] + bb[2], acc[i][3] + bb[3]};
        *(float4*)&out[(size_t)(m0 + ty * 8 + i) * DM + n0 + tx * 4] = v;
    }
}

// ---------------------------------------------------------------------------
extern "C" void kernel_launch(void* const* d_in, const int* in_sizes, int n_in,
                              void* d_out, int out_size)
{
    const float* x  = (const float*)d_in[0];
    const float* Wq = (const float*)d_in[1];
    const float* bq = (const float*)d_in[2];
    const float* Wk = (const float*)d_in[3];
    const float* bk = (const float*)d_in[4];
    const float* Wv = (const float*)d_in[5];
    const float* bv = (const float*)d_in[6];
    const float* Wo = (const float*)d_in[7];
    const float* bo = (const float*)d_in[8];
    float* out = (float*)d_out;

    const size_t att_smem = (size_t)ATT_SMEM_FLOATS * sizeof(float); // ~98.5 KB
    cudaFuncSetAttribute(attn_kernel, cudaFuncAttributeMaxDynamicSharedMemorySize,
                         (int)att_smem);

    qkv_kernel<<<dim3(64, 16, 3), 256>>>(x, Wq, bq, Wk, bk, Wv, bv);
    attn_kernel<<<dim3(16, 64), 256, att_smem>>>();
    out_proj_kernel<<<dim3(64, 16), 256>>>(Wo, bo, out);
}

// round 3
// speedup vs baseline: 1.4068x; 1.4068x over previous
#include <cuda_runtime.h>
#include <cuda_bf16.h>
#include <math.h>
#include <cstdint>

#define B 4
#define H 16
#define S 2048
#define DM 1024
#define DH 64
#define SCALE 0.125f
#define NTOK (B*S)   // 8192

// ---------------------------------------------------------------------------
// Scratch (device globals: no allocations allowed)
// ---------------------------------------------------------------------------
__device__ float g_q[(size_t)B*H*S*DH];      // [b][h][s][e]
__device__ float g_kt[(size_t)B*H*DH*S];     // [b][h][e][s]
__device__ float g_v[(size_t)B*H*S*DH];      // [b][h][s][e]
__device__ float g_heads[(size_t)B*S*DM];    // [b][s][h*64+e]

// split-bf16 operands
__device__ __nv_bfloat16 gx_hi[(size_t)NTOK*DM], gx_lo[(size_t)NTOK*DM];
__device__ __nv_bfloat16 gw_hi[(size_t)3*H*DH*DM], gw_lo[(size_t)3*H*DH*DM];  // [(which*16+h)*64+e][d]
__device__ __nv_bfloat16 gwo_hi[(size_t)DM*DM], gwo_lo[(size_t)DM*DM];        // [n][k]
__device__ __nv_bfloat16 gh_hi[(size_t)NTOK*DM], gh_lo[(size_t)NTOK*DM];

// ---------------------------------------------------------------------------
// mma / ldmatrix helpers (sm_80-level PTX, valid under compute_103)
// ---------------------------------------------------------------------------
__device__ __forceinline__ uint32_t smem_u32(const void* p) {
    uint32_t a;
    asm("{ .reg .u64 t; cvta.to.shared.u64 t, %1; cvt.u32.u64 %0, t; }" : "=r"(a) : "l"(p));
    return a;
}

#define LDSM_X4(r0, r1, r2, r3, addr) \
    asm volatile("ldmatrix.sync.aligned.m8n8.x4.shared.b16 {%0,%1,%2,%3}, [%4];" \
                 : "=r"(r0), "=r"(r1), "=r"(r2), "=r"(r3) : "r"(addr))
#define LDSM_X2(r0, r1, addr) \
    asm volatile("ldmatrix.sync.aligned.m8n8.x2.shared.b16 {%0,%1}, [%2];" \
                 : "=r"(r0), "=r"(r1) : "r"(addr))

__device__ __forceinline__ void mma_bf16(float* c, const uint32_t* a, const uint32_t* b) {
    asm volatile("mma.sync.aligned.m16n8k16.row.col.f32.bf16.bf16.f32 "
                 "{%0,%1,%2,%3}, {%4,%5,%6,%7}, {%8,%9}, {%0,%1,%2,%3};"
                 : "+f"(c[0]), "+f"(c[1]), "+f"(c[2]), "+f"(c[3])
                 : "r"(a[0]), "r"(a[1]), "r"(a[2]), "r"(a[3]), "r"(b[0]), "r"(b[1]));
}

// ---------------------------------------------------------------------------
// Split helpers & conversion kernels
// ---------------------------------------------------------------------------
__device__ __forceinline__ void split2(float a, __nv_bfloat16& h, __nv_bfloat16& l) {
    h = __float2bfloat16(a);
    l = __float2bfloat16(a - __bfloat162float(h));
}

__global__ __launch_bounds__(256) void split_kernel(const float* __restrict__ src,
        __nv_bfloat16* __restrict__ hi, __nv_bfloat16* __restrict__ lo) {
    int i = blockIdx.x * 256 + threadIdx.x;   // one float4
    float4 v = ((const float4*)src)[i];
    __nv_bfloat16 h0,h1,h2,h3,l0,l1,l2,l3;
    split2(v.x,h0,l0); split2(v.y,h1,l1); split2(v.z,h2,l2); split2(v.w,h3,l3);
    __nv_bfloat162* hp = (__nv_bfloat162*)hi;
    __nv_bfloat162* lp = (__nv_bfloat162*)lo;
    __nv_bfloat162 t;
    t.x=h0; t.y=h1; hp[2*i]   = t;
    t.x=h2; t.y=h3; hp[2*i+1] = t;
    t.x=l0; t.y=l1; lp[2*i]   = t;
    t.x=l2; t.y=l3; lp[2*i+1] = t;
}

// transpose + split: src row-major [K,N] (per blockIdx.y sub-matrix) -> out[(y*N+n)*K+k]
__global__ __launch_bounds__(256) void tsplit_kernel(const float* __restrict__ src,
        __nv_bfloat16* __restrict__ hi, __nv_bfloat16* __restrict__ lo, int K, int N) {
    src += (size_t)blockIdx.y * K * N;
    size_t obase = ((size_t)blockIdx.y * N + blockIdx.x) * K;
    for (int k = threadIdx.x; k < K; k += 256) {
        float a = src[(size_t)k * N + blockIdx.x];
        __nv_bfloat16 h, l; split2(a, h, l);
        hi[obase + k] = h; lo[obase + k] = l;
    }
}

// ---------------------------------------------------------------------------
// HMMA GEMM core: per block a 128(M) x 64(N) tile of A[M,1024] @ B[64,1024]^T.
// A row-major [m][k], B rows [n][k] (== .col operand). split-bf16, fp32 acc.
// 8 warps, each a 32x32 warp tile = 2(m) x 4(n) mma.m16n8k16 tiles.
// Smem stage: K=64 halves, pitch 72 halves (conflict-free ldmatrix).
// ---------------------------------------------------------------------------
#define PA 72
#define SM_AHI 0
#define SM_ALO (128 * PA)
#define SM_BHI (2 * 128 * PA)
#define SM_BLO (2 * 128 * PA + 64 * PA)
#define GSM_HALVES (2 * 128 * PA + 2 * 64 * PA)   // 27648 halves = 55296 B
#define GSM_BYTES (GSM_HALVES * 2)

__device__ __forceinline__ void gemm_tile_mma(
    const __nv_bfloat16* __restrict__ a_hi, const __nv_bfloat16* __restrict__ a_lo, size_t arow0,
    const __nv_bfloat16* __restrict__ b_hi, const __nv_bfloat16* __restrict__ b_lo, size_t brow0,
    float acc[2][4][4])
{
    extern __shared__ __nv_bfloat16 sm[];
    const int tid = threadIdx.x;
    const int wid = tid >> 5, lane = tid & 31;
    const int base_m = (wid >> 1) * 32;
    const int base_n = (wid & 1) * 32;

    #pragma unroll
    for (int im = 0; im < 2; im++)
        #pragma unroll
        for (int in_ = 0; in_ < 4; in_++)
            #pragma unroll
            for (int v = 0; v < 4; v++) acc[im][in_][v] = 0.f;

    // precompute ldmatrix smem addrs (stage-invariant parts)
    const uint32_t smb = smem_u32(sm);
    // A: row = base_m + im*16 + (lane&15); coloff = ks*16 + ((lane>>4)<<3)
    const int a_row_l = (lane & 15);
    const int a_col_l = ((lane >> 4) << 3);
    // B: row = base_n + in*8 + (lane&7); coloff = ks*16 + (((lane>>3)&1)<<3)
    const int b_row_l = (lane & 7);
    const int b_col_l = (((lane >> 3) & 1) << 3);

    for (int s = 0; s < DM / 64; s++) {
        const int k0 = s * 64;
        // ---- load stage ----
        #pragma unroll
        for (int it = 0; it < 4; it++) {            // A: 128 rows x 8 chunks of 8 halves
            int c = it * 256 + tid;
            int row = c >> 3, c8 = c & 7;
            size_t gidx = (arow0 + row) * (size_t)DM + k0 + c8 * 8;
            *(uint4*)&sm[SM_AHI + row * PA + c8 * 8] = *(const uint4*)(a_hi + gidx);
            *(uint4*)&sm[SM_ALO + row * PA + c8 * 8] = *(const uint4*)(a_lo + gidx);
        }
        #pragma unroll
        for (int it = 0; it < 2; it++) {            // B: 64 rows x 8 chunks
            int c = it * 256 + tid;
            int row = c >> 3, c8 = c & 7;
            size_t gidx = (brow0 + row) * (size_t)DM + k0 + c8 * 8;
            *(uint4*)&sm[SM_BHI + row * PA + c8 * 8] = *(const uint4*)(b_hi + gidx);
            *(uint4*)&sm[SM_BLO + row * PA + c8 * 8] = *(const uint4*)(b_lo + gidx);
        }
        __syncthreads();

        // ---- compute 4 k16 steps ----
        #pragma unroll
        for (int ks = 0; ks < 4; ks++) {
            uint32_t ah[2][4], al[2][4], bh[4][2], bl[4][2];
            #pragma unroll
            for (int im = 0; im < 2; im++) {
                uint32_t off = (uint32_t)((base_m + im * 16 + a_row_l) * PA
                                          + ks * 16 + a_col_l) * 2;
                LDSM_X4(ah[im][0], ah[im][1], ah[im][2], ah[im][3],
                        smb + SM_AHI * 2 + off);
                LDSM_X4(al[im][0], al[im][1], al[im][2], al[im][3],
                        smb + SM_ALO * 2 + off);
            }
            #pragma unroll
            for (int in_ = 0; in_ < 4; in_++) {
                uint32_t off = (uint32_t)((base_n + in_ * 8 + b_row_l) * PA
                                          + ks * 16 + b_col_l) * 2;
                LDSM_X2(bh[in_][0], bh[in_][1], smb + SM_BHI * 2 + off);
                LDSM_X2(bl[in_][0], bl[in_][1], smb + SM_BLO * 2 + off);
            }
            #pragma unroll
            for (int im = 0; im < 2; im++)
                #pragma unroll
                for (int in_ = 0; in_ < 4; in_++) {
                    mma_bf16(acc[im][in_], ah[im], bh[in_]);
                    mma_bf16(acc[im][in_], ah[im], bl[in_]);
                    mma_bf16(acc[im][in_], al[im], bh[in_]);
                }
        }
        __syncthreads();
    }
}

// ---------------------------------------------------------------------------
// QKV GEMM: grid (64 mtiles, 48 ntiles). ntile -> which (0=q,1=k,2=v), head.
// ---------------------------------------------------------------------------
__global__ __launch_bounds__(256) void gemm_qkv_tc(
    const float* __restrict__ bq, const float* __restrict__ bk, const float* __restrict__ bv)
{
    const int mt = blockIdx.x, nt = blockIdx.y;
    const int which = nt / H, h = nt % H;
    const size_t arow0 = (size_t)mt * 128;
    const size_t brow0 = (size_t)nt * 64;

    float acc[2][4][4];
    gemm_tile_mma(gx_hi, gx_lo, arow0, gw_hi, gw_lo, brow0, acc);

    const int tid = threadIdx.x, wid = tid >> 5, lane = tid & 31;
    const int base_m = (wid >> 1) * 32;
    const int base_n = (wid & 1) * 32;
    const float* bias = (which == 0) ? bq : (which == 1) ? bk : bv;

    #pragma unroll
    for (int im = 0; im < 2; im++) {
        #pragma unroll
        for (int in_ = 0; in_ < 4; in_++) {
            #pragma unroll
            for (int half = 0; half < 2; half++) {
                int r = base_m + im * 16 + (lane >> 2) + half * 8;
                int c = base_n + in_ * 8 + (lane & 3) * 2;
                size_t m = arow0 + r;
                int b = (int)(m / S), sidx = (int)(m % S);
                int bhidx = b * H + h;
                float v0 = acc[im][in_][half * 2 + 0] + bias[h * DH + c];
                float v1 = acc[im][in_][half * 2 + 1] + bias[h * DH + c + 1];
                if (which == 1) {
                    g_kt[((size_t)bhidx * DH + c)     * S + sidx] = v0;
                    g_kt[((size_t)bhidx * DH + c + 1) * S + sidx] = v1;
                } else {
                    float* dst = (which == 0) ? g_q : g_v;
                    float2 w = {v0, v1};
                    *(float2*)&dst[((size_t)bhidx * S + sidx) * DH + c] = w;
                }
            }
        }
    }
}

// ---------------------------------------------------------------------------
// Output GEMM: grid (64 mtiles, 16 ntiles of 64).
// ---------------------------------------------------------------------------
__global__ __launch_bounds__(256) void gemm_out_tc(const float* __restrict__ bo,
                                                   float* __restrict__ out)
{
    const int mt = blockIdx.x, nt = blockIdx.y;
    const size_t arow0 = (size_t)mt * 128;

    float acc[2][4][4];
    gemm_tile_mma(gh_hi, gh_lo, arow0, gwo_hi, gwo_lo, (size_t)nt * 64, acc);

    const int tid = threadIdx.x, wid = tid >> 5, lane = tid & 31;
    const int base_m = (wid >> 1) * 32;
    const int base_n = (wid & 1) * 32;

    #pragma unroll
    for (int im = 0; im < 2; im++) {
        #pragma unroll
        for (int in_ = 0; in_ < 4; in_++) {
            #pragma unroll
            for (int half = 0; half < 2; half++) {
                int r = base_m + im * 16 + (lane >> 2) + half * 8;
                int c = nt * 64 + base_n + in_ * 8 + (lane & 3) * 2;
                size_t m = arow0 + r;
                float2 w = {acc[im][in_][half * 2 + 0] + bo[c],
                            acc[im][in_][half * 2 + 1] + bo[c + 1]};
                *(float2*)&out[m * DM + c] = w;
            }
        }
    }
}

// ---------------------------------------------------------------------------
// Attention (fp32 flash-style, validated in R1)
// ---------------------------------------------------------------------------
#define QS_P 129
#define KS_P 68
#define VS_P 68
#define PS_P 129
#define QS_OFF 0
#define KS_OFF (64 * QS_P)
#define VS_OFF (KS_OFF + 64 * KS_P)
#define PS_OFF (VS_OFF + 64 * VS_P)
#define ATT_SMEM_FLOATS (PS_OFF + 64 * PS_P)

__global__ __launch_bounds__(256, 2) void attn_kernel()
{
    extern __shared__ float smf[];
    float* qs = smf + QS_OFF;
    float* ks = smf + KS_OFF;
    float* vs = smf + VS_OFF;
    float* ps = smf + PS_OFF;

    const int qt = blockIdx.x;
    const int bh = blockIdx.y;
    const int s0 = qt * 128;
    const int tid = threadIdx.x;
    const int tx = tid & 15, ty = tid >> 4;

    {
        int c  = tid & 15;
        int r0 = tid >> 4;
        #pragma unroll
        for (int p = 0; p < 8; p++) {
            int r = r0 + p * 16;
            float4 v = *(const float4*)&g_q[((size_t)bh * S + s0 + r) * DH + c * 4];
            qs[(c*4+0)*QS_P + r] = v.x * SCALE;
            qs[(c*4+1)*QS_P + r] = v.y * SCALE;
            qs[(c*4+2)*QS_P + r] = v.z * SCALE;
            qs[(c*4+3)*QS_P + r] = v.w * SCALE;
        }
    }
    __syncthreads();

    float o[8][4];
    float m[8], l[8];
    #pragma unroll
    for (int i = 0; i < 8; i++) {
        m[i] = -INFINITY; l[i] = 0.f;
        #pragma unroll
        for (int j = 0; j < 4; j++) o[i][j] = 0.f;
    }

    for (int kt = 0; kt < S / 64; kt++) {
        {
            int c = tid & 15;
            int d0 = tid >> 4;
            #pragma unroll
            for (int p = 0; p < 4; p++) {
                int d = d0 + p * 16;
                float4 v = *(const float4*)&g_kt[((size_t)bh * DH + d) * S + kt * 64 + c * 4];
                *(float4*)&ks[d * KS_P + c * 4] = v;
            }
        }
        {
            int c = tid & 15;
            int r0 = tid >> 4;
            #pragma unroll
            for (int p = 0; p < 4; p++) {
                int r = r0 + p * 16;
                float4 v = *(const float4*)&g_v[((size_t)bh * S + kt * 64 + r) * DH + c * 4];
                *(float4*)&vs[r * VS_P + c * 4] = v;
            }
        }
        __syncthreads();

        float sc[8][4];
        #pragma unroll
        for (int i = 0; i < 8; i++)
            #pragma unroll
            for (int j = 0; j < 4; j++) sc[i][j] = 0.f;
        #pragma unroll 4
        for (int kk = 0; kk < 64; kk++) {
            float a[8];
            #pragma unroll
            for (int i = 0; i < 8; i++) a[i] = qs[kk * QS_P + ty * 8 + i];
            float4 bv4 = *(float4*)&ks[kk * KS_P + tx * 4];
            float bb[4] = {bv4.x, bv4.y, bv4.z, bv4.w};
            #pragma unroll
            for (int i = 0; i < 8; i++)
                #pragma unroll
                for (int j = 0; j < 4; j++)
                    sc[i][j] += a[i] * bb[j];
        }

        #pragma unroll
        for (int i = 0; i < 8; i++) {
            float mx = fmaxf(fmaxf(sc[i][0], sc[i][1]), fmaxf(sc[i][2], sc[i][3]));
            #pragma unroll
            for (int off = 8; off >= 1; off >>= 1)
                mx = fmaxf(mx, __shfl_xor_sync(0xffffffffu, mx, off));
            float mnew = fmaxf(m[i], mx);
            float f = __expf(m[i] - mnew);
            m[i] = mnew;
            float rs = 0.f;
            #pragma unroll
            for (int j = 0; j < 4; j++) {
                sc[i][j] = __expf(sc[i][j] - mnew);
                rs += sc[i][j];
            }
            #pragma unroll
            for (int off = 8; off >= 1; off >>= 1)
                rs += __shfl_xor_sync(0xffffffffu, rs, off);
            l[i] = l[i] * f + rs;
            #pragma unroll
            for (int j = 0; j < 4; j++) o[i][j] *= f;
            #pragma unroll
            for (int j = 0; j < 4; j++)
                ps[(tx * 4 + j) * PS_P + ty * 8 + i] = sc[i][j];
        }
        __syncthreads();

        #pragma unroll 4
        for (int ck = 0; ck < 64; ck++) {
            float a[8];
            #pragma unroll
            for (int i = 0; i < 8; i++) a[i] = ps[ck * PS_P + ty * 8 + i];
            float4 bv4 = *(float4*)&vs[ck * VS_P + tx * 4];
            float bb[4] = {bv4.x, bv4.y, bv4.z, bv4.w};
            #pragma unroll
            for (int i = 0; i < 8; i++)
                #pragma unroll
                for (int j = 0; j < 4; j++)
                    o[i][j] += a[i] * bb[j];
        }
        __syncthreads();
    }

    const int b = bh >> 4;
    const int h = bh & 15;
    #pragma unroll
    for (int i = 0; i < 8; i++) {
        float inv = 1.f / l[i];
        float4 v = {o[i][0] * inv, o[i][1] * inv, o[i][2] * inv, o[i][3] * inv};
        *(float4*)&g_heads[((size_t)b * S + s0 + ty * 8 + i) * DM + h * DH + tx * 4] = v;
    }
}

// ---------------------------------------------------------------------------
extern "C" void kernel_launch(void* const* d_in, const int* in_sizes, int n_in,
                              void* d_out, int out_size)
{
    const float* x  = (const float*)d_in[0];
    const float* Wq = (const float*)d_in[1];
    const float* bq = (const float*)d_in[2];
    const float* Wk = (const float*)d_in[3];
    const float* bk = (const float*)d_in[4];
    const float* Wv = (const float*)d_in[5];
    const float* bv = (const float*)d_in[6];
    const float* Wo = (const float*)d_in[7];
    const float* bo = (const float*)d_in[8];
    float* out = (float*)d_out;

    static __nv_bfloat16 *p_gxh, *p_gxl, *p_gwh, *p_gwl, *p_gwoh, *p_gwol, *p_ghh, *p_ghl;
    static float* p_heads;
    static bool init = false;
    if (!init) {
        cudaGetSymbolAddress((void**)&p_gxh,  gx_hi);
        cudaGetSymbolAddress((void**)&p_gxl,  gx_lo);
        cudaGetSymbolAddress((void**)&p_gwh,  gw_hi);
        cudaGetSymbolAddress((void**)&p_gwl,  gw_lo);
        cudaGetSymbolAddress((void**)&p_gwoh, gwo_hi);
        cudaGetSymbolAddress((void**)&p_gwol, gwo_lo);
        cudaGetSymbolAddress((void**)&p_ghh,  gh_hi);
        cudaGetSymbolAddress((void**)&p_ghl,  gh_lo);
        cudaGetSymbolAddress((void**)&p_heads, g_heads);
        cudaFuncSetAttribute(attn_kernel, cudaFuncAttributeMaxDynamicSharedMemorySize,
                             (int)((size_t)ATT_SMEM_FLOATS * sizeof(float)));
        cudaFuncSetAttribute(gemm_qkv_tc, cudaFuncAttributeMaxDynamicSharedMemorySize, GSM_BYTES);
        cudaFuncSetAttribute(gemm_out_tc, cudaFuncAttributeMaxDynamicSharedMemorySize, GSM_BYTES);
        init = true;
    }

    const size_t att_smem = (size_t)ATT_SMEM_FLOATS * sizeof(float);

    // 1. split inputs to bf16 hi/lo
    split_kernel<<<(NTOK * DM / 4) / 256, 256>>>(x, p_gxh, p_gxl);
    tsplit_kernel<<<dim3(DH, H), 256>>>(Wq, p_gwh,                     p_gwl,                     DM, DH);
    tsplit_kernel<<<dim3(DH, H), 256>>>(Wk, p_gwh + (size_t)H*DH*DM,   p_gwl + (size_t)H*DH*DM,   DM, DH);
    tsplit_kernel<<<dim3(DH, H), 256>>>(Wv, p_gwh + (size_t)2*H*DH*DM, p_gwl + (size_t)2*H*DH*DM, DM, DH);
    tsplit_kernel<<<dim3(DM, 1), 256>>>(Wo, p_gwoh, p_gwol, DM, DM);

    // 2. QKV projection on tensor cores (HMMA)
    gemm_qkv_tc<<<dim3(64, 48), 256, GSM_BYTES>>>(bq, bk, bv);

    // 3. attention (fp32)
    attn_kernel<<<dim3(16, 64), 256, att_smem>>>();

    // 4. split heads, output projection on tensor cores
    split_kernel<<<(NTOK * DM / 4) / 256, 256>>>(p_heads, p_ghh, p_ghl);
    gemm_out_tc<<<dim3(64, 16), 256, GSM_BYTES>>>(bo, out);
}

// round 4
// speedup vs baseline: 2.3069x; 1.6398x over previous
#include <cuda_runtime.h>
#include <cuda_bf16.h>
#include <math.h>
#include <cstdint>

#define B 4
#define H 16
#define S 2048
#define DM 1024
#define DH 64
#define SCALE 0.125f
#define NTOK (B*S)   // 8192

// ---------------------------------------------------------------------------
// Scratch (device globals: no allocations allowed)
// ---------------------------------------------------------------------------
// split-bf16 GEMM operands
__device__ __nv_bfloat16 gx_hi[(size_t)NTOK*DM], gx_lo[(size_t)NTOK*DM];
__device__ __nv_bfloat16 gw_hi[(size_t)3*H*DH*DM], gw_lo[(size_t)3*H*DH*DM];  // [(which*16+h)*64+e][d]
__device__ __nv_bfloat16 gwo_hi[(size_t)DM*DM], gwo_lo[(size_t)DM*DM];        // [n][k]
__device__ __nv_bfloat16 gh_hi[(size_t)NTOK*DM], gh_lo[(size_t)NTOK*DM];      // heads (attn out)

// attention operands (split bf16, produced by qkv GEMM)
__device__ __nv_bfloat16 gq_hi[(size_t)B*H*S*DH], gq_lo[(size_t)B*H*S*DH];    // [bh][s][e], pre-scaled
__device__ __nv_bfloat16 gk_hi[(size_t)B*H*S*DH], gk_lo[(size_t)B*H*S*DH];    // [bh][s][e]
__device__ __nv_bfloat16 gvt_hi[(size_t)B*H*DH*S], gvt_lo[(size_t)B*H*DH*S];  // [bh][e][s]

// ---------------------------------------------------------------------------
// mma / ldmatrix helpers (sm_80-level PTX, valid under compute_103)
// ---------------------------------------------------------------------------
__device__ __forceinline__ uint32_t smem_u32(const void* p) {
    uint32_t a;
    asm("{ .reg .u64 t; cvta.to.shared.u64 t, %1; cvt.u32.u64 %0, t; }" : "=r"(a) : "l"(p));
    return a;
}

#define LDSM_X4(r0, r1, r2, r3, addr) \
    asm volatile("ldmatrix.sync.aligned.m8n8.x4.shared.b16 {%0,%1,%2,%3}, [%4];" \
                 : "=r"(r0), "=r"(r1), "=r"(r2), "=r"(r3) : "r"(addr))
#define LDSM_X2(r0, r1, addr) \
    asm volatile("ldmatrix.sync.aligned.m8n8.x2.shared.b16 {%0,%1}, [%2];" \
                 : "=r"(r0), "=r"(r1) : "r"(addr))

__device__ __forceinline__ void mma_bf16(float* c, const uint32_t* a, const uint32_t* b) {
    asm volatile("mma.sync.aligned.m16n8k16.row.col.f32.bf16.bf16.f32 "
                 "{%0,%1,%2,%3}, {%4,%5,%6,%7}, {%8,%9}, {%0,%1,%2,%3};"
                 : "+f"(c[0]), "+f"(c[1]), "+f"(c[2]), "+f"(c[3])
                 : "r"(a[0]), "r"(a[1]), "r"(a[2]), "r"(a[3]), "r"(b[0]), "r"(b[1]));
}

// ---------------------------------------------------------------------------
// Split helpers & conversion kernels
// ---------------------------------------------------------------------------
__device__ __forceinline__ void split2(float a, __nv_bfloat16& h, __nv_bfloat16& l) {
    h = __float2bfloat16(a);
    l = __float2bfloat16(a - __bfloat162float(h));
}

__global__ __launch_bounds__(256) void split_kernel(const float* __restrict__ src,
        __nv_bfloat16* __restrict__ hi, __nv_bfloat16* __restrict__ lo) {
    int i = blockIdx.x * 256 + threadIdx.x;   // one float4
    float4 v = ((const float4*)src)[i];
    __nv_bfloat16 h0,h1,h2,h3,l0,l1,l2,l3;
    split2(v.x,h0,l0); split2(v.y,h1,l1); split2(v.z,h2,l2); split2(v.w,h3,l3);
    __nv_bfloat162* hp = (__nv_bfloat162*)hi;
    __nv_bfloat162* lp = (__nv_bfloat162*)lo;
    __nv_bfloat162 t;
    t.x=h0; t.y=h1; hp[2*i]   = t;
    t.x=h2; t.y=h3; hp[2*i+1] = t;
    t.x=l0; t.y=l1; lp[2*i]   = t;
    t.x=l2; t.y=l3; lp[2*i+1] = t;
}

// transpose + split: src row-major [K,N] (per blockIdx.y sub-matrix) -> out[(y*N+n)*K+k]
__global__ __launch_bounds__(256) void tsplit_kernel(const float* __restrict__ src,
        __nv_bfloat16* __restrict__ hi, __nv_bfloat16* __restrict__ lo, int K, int N) {
    src += (size_t)blockIdx.y * K * N;
    size_t obase = ((size_t)blockIdx.y * N + blockIdx.x) * K;
    for (int k = threadIdx.x; k < K; k += 256) {
        float a = src[(size_t)k * N + blockIdx.x];
        __nv_bfloat16 h, l; split2(a, h, l);
        hi[obase + k] = h; lo[obase + k] = l;
    }
}

// ---------------------------------------------------------------------------
// HMMA GEMM core (validated in R3): 128(M) x 64(N) tile of A[M,1024] @ B[64,1024]^T
// ---------------------------------------------------------------------------
#define PA 72
#define SM_AHI 0
#define SM_ALO (128 * PA)
#define SM_BHI (2 * 128 * PA)
#define SM_BLO (2 * 128 * PA + 64 * PA)
#define GSM_HALVES (2 * 128 * PA + 2 * 64 * PA)
#define GSM_BYTES (GSM_HALVES * 2)

__device__ __forceinline__ void gemm_tile_mma(
    const __nv_bfloat16* __restrict__ a_hi, const __nv_bfloat16* __restrict__ a_lo, size_t arow0,
    const __nv_bfloat16* __restrict__ b_hi, const __nv_bfloat16* __restrict__ b_lo, size_t brow0,
    float acc[2][4][4])
{
    extern __shared__ __nv_bfloat16 sm[];
    const int tid = threadIdx.x;
    const int wid = tid >> 5, lane = tid & 31;
    const int base_m = (wid >> 1) * 32;
    const int base_n = (wid & 1) * 32;

    #pragma unroll
    for (int im = 0; im < 2; im++)
        #pragma unroll
        for (int in_ = 0; in_ < 4; in_++)
            #pragma unroll
            for (int v = 0; v < 4; v++) acc[im][in_][v] = 0.f;

    const uint32_t smb = smem_u32(sm);
    const int a_row_l = (lane & 15);
    const int a_col_l = ((lane >> 4) << 3);
    const int b_row_l = (lane & 7);
    const int b_col_l = (((lane >> 3) & 1) << 3);

    for (int s = 0; s < DM / 64; s++) {
        const int k0 = s * 64;
        #pragma unroll
        for (int it = 0; it < 4; it++) {
            int c = it * 256 + tid;
            int row = c >> 3, c8 = c & 7;
            size_t gidx = (arow0 + row) * (size_t)DM + k0 + c8 * 8;
            *(uint4*)&sm[SM_AHI + row * PA + c8 * 8] = *(const uint4*)(a_hi + gidx);
            *(uint4*)&sm[SM_ALO + row * PA + c8 * 8] = *(const uint4*)(a_lo + gidx);
        }
        #pragma unroll
        for (int it = 0; it < 2; it++) {
            int c = it * 256 + tid;
            int row = c >> 3, c8 = c & 7;
            size_t gidx = (brow0 + row) * (size_t)DM + k0 + c8 * 8;
            *(uint4*)&sm[SM_BHI + row * PA + c8 * 8] = *(const uint4*)(b_hi + gidx);
            *(uint4*)&sm[SM_BLO + row * PA + c8 * 8] = *(const uint4*)(b_lo + gidx);
        }
        __syncthreads();

        #pragma unroll
        for (int ks = 0; ks < 4; ks++) {
            uint32_t ah[2][4], al[2][4], bh[4][2], bl[4][2];
            #pragma unroll
            for (int im = 0; im < 2; im++) {
                uint32_t off = (uint32_t)((base_m + im * 16 + a_row_l) * PA
                                          + ks * 16 + a_col_l) * 2;
                LDSM_X4(ah[im][0], ah[im][1], ah[im][2], ah[im][3], smb + SM_AHI * 2 + off);
                LDSM_X4(al[im][0], al[im][1], al[im][2], al[im][3], smb + SM_ALO * 2 + off);
            }
            #pragma unroll
            for (int in_ = 0; in_ < 4; in_++) {
                uint32_t off = (uint32_t)((base_n + in_ * 8 + b_row_l) * PA
                                          + ks * 16 + b_col_l) * 2;
                LDSM_X2(bh[in_][0], bh[in_][1], smb + SM_BHI * 2 + off);
                LDSM_X2(bl[in_][0], bl[in_][1], smb + SM_BLO * 2 + off);
            }
            #pragma unroll
            for (int im = 0; im < 2; im++)
                #pragma unroll
                for (int in_ = 0; in_ < 4; in_++) {
                    mma_bf16(acc[im][in_], ah[im], bh[in_]);
                    mma_bf16(acc[im][in_], ah[im], bl[in_]);
                    mma_bf16(acc[im][in_], al[im], bh[in_]);
                }
        }
        __syncthreads();
    }
}

// ---------------------------------------------------------------------------
// QKV GEMM: epilogue writes split-bf16 Q (scaled), K, V^T.
// ---------------------------------------------------------------------------
__global__ __launch_bounds__(256) void gemm_qkv_tc(
    const float* __restrict__ bq, const float* __restrict__ bk, const float* __restrict__ bv)
{
    const int mt = blockIdx.x, nt = blockIdx.y;
    const int which = nt / H, h = nt % H;
    const size_t arow0 = (size_t)mt * 128;
    const size_t brow0 = (size_t)nt * 64;

    float acc[2][4][4];
    gemm_tile_mma(gx_hi, gx_lo, arow0, gw_hi, gw_lo, brow0, acc);

    const int tid = threadIdx.x, wid = tid >> 5, lane = tid & 31;
    const int base_m = (wid >> 1) * 32;
    const int base_n = (wid & 1) * 32;
    const float* bias = (which == 0) ? bq : (which == 1) ? bk : bv;

    #pragma unroll
    for (int im = 0; im < 2; im++) {
        #pragma unroll
        for (int in_ = 0; in_ < 4; in_++) {
            #pragma unroll
            for (int half = 0; half < 2; half++) {
                int r = base_m + im * 16 + (lane >> 2) + half * 8;
                int c = base_n + in_ * 8 + (lane & 3) * 2;
                size_t m = arow0 + r;
                int b = (int)(m / S), sidx = (int)(m % S);
                int bhidx = b * H + h;
                float v0 = acc[im][in_][half * 2 + 0] + bias[h * DH + c];
                float v1 = acc[im][in_][half * 2 + 1] + bias[h * DH + c + 1];
                if (which == 0) { v0 *= SCALE; v1 *= SCALE; }
                __nv_bfloat16 h0, l0, h1, l1;
                split2(v0, h0, l0); split2(v1, h1, l1);
                if (which == 2) {
                    size_t base = ((size_t)bhidx * DH + c) * S + sidx;
                    gvt_hi[base] = h0;     gvt_lo[base] = l0;
                    gvt_hi[base + S] = h1; gvt_lo[base + S] = l1;
                } else {
                    __nv_bfloat16* dh = (which == 0) ? gq_hi : gk_hi;
                    __nv_bfloat16* dl = (which == 0) ? gq_lo : gk_lo;
                    size_t base = ((size_t)bhidx * S + sidx) * DH + c;
                    __nv_bfloat162 th; th.x = h0; th.y = h1;
                    __nv_bfloat162 tl; tl.x = l0; tl.y = l1;
                    *(__nv_bfloat162*)&dh[base] = th;
                    *(__nv_bfloat162*)&dl[base] = tl;
                }
            }
        }
    }
}

// ---------------------------------------------------------------------------
// Output GEMM: grid (64 mtiles, 16 ntiles of 64).
// ---------------------------------------------------------------------------
__global__ __launch_bounds__(256) void gemm_out_tc(const float* __restrict__ bo,
                                                   float* __restrict__ out)
{
    const int mt = blockIdx.x, nt = blockIdx.y;
    const size_t arow0 = (size_t)mt * 128;

    float acc[2][4][4];
    gemm_tile_mma(gh_hi, gh_lo, arow0, gwo_hi, gwo_lo, (size_t)nt * 64, acc);

    const int tid = threadIdx.x, wid = tid >> 5, lane = tid & 31;
    const int base_m = (wid >> 1) * 32;
    const int base_n = (wid & 1) * 32;

    #pragma unroll
    for (int im = 0; im < 2; im++) {
        #pragma unroll
        for (int in_ = 0; in_ < 4; in_++) {
            #pragma unroll
            for (int half = 0; half < 2; half++) {
                int r = base_m + im * 16 + (lane >> 2) + half * 8;
                int c = nt * 64 + base_n + in_ * 8 + (lane & 3) * 2;
                size_t m = arow0 + r;
                float2 w = {acc[im][in_][half * 2 + 0] + bo[c],
                            acc[im][in_][half * 2 + 1] + bo[c + 1]};
                *(float2*)&out[m * DM + c] = w;
            }
        }
    }
}

// ---------------------------------------------------------------------------
// Attention on HMMA (FA2 style, split-bf16 for both MMAs).
// Block: 128 q rows x 1 (b,h). 8 warps, each 16 rows x all 64 cols.
// ---------------------------------------------------------------------------
#define A_QHI 0
#define A_QLO (128 * PA)
#define A_KHI (2 * 128 * PA)
#define A_KLO (A_KHI + 64 * PA)
#define A_VHI (A_KLO + 64 * PA)
#define A_VLO (A_VHI + 64 * PA)
#define ATT_HALVES (A_VLO + 64 * PA)
#define ATT_BYTES (ATT_HALVES * 2)     // 73728

__global__ __launch_bounds__(256) void attn_mma()
{
    extern __shared__ __nv_bfloat16 sm[];
    const int qt = blockIdx.x;
    const int bh = blockIdx.y;
    const int tid = threadIdx.x, wid = tid >> 5, lane = tid & 31;
    const int base_m = wid * 16;
    const uint32_t smb = smem_u32(sm);
    const int a_row_l = (lane & 15);
    const int a_col_l = ((lane >> 4) << 3);
    const int b_row_l = (lane & 7);
    const int b_col_l = (((lane >> 3) & 1) << 3);

    // load Q tile (128x64, hi+lo), already scaled
    const size_t qbase = ((size_t)bh * S + qt * 128) * DH;
    #pragma unroll
    for (int it = 0; it < 4; it++) {
        int c = it * 256 + tid;
        int row = c >> 3, c8 = c & 7;
        *(uint4*)&sm[A_QHI + row * PA + c8 * 8] = *(const uint4*)(gq_hi + qbase + (size_t)row * DH + c8 * 8);
        *(uint4*)&sm[A_QLO + row * PA + c8 * 8] = *(const uint4*)(gq_lo + qbase + (size_t)row * DH + c8 * 8);
    }

    float o[8][4];
    #pragma unroll
    for (int nt = 0; nt < 8; nt++)
        #pragma unroll
        for (int v = 0; v < 4; v++) o[nt][v] = 0.f;
    float mrow[2] = {-INFINITY, -INFINITY};
    float lrow[2] = {0.f, 0.f};

    for (int kt = 0; kt < S / 64; kt++) {
        // load K tile 64x64 (hi/lo) and V^T tile 64(e)x64(kv) (hi/lo)
        const size_t kbase = ((size_t)bh * S + kt * 64) * DH;
        #pragma unroll
        for (int it = 0; it < 2; it++) {
            int c = it * 256 + tid;
            int row = c >> 3, c8 = c & 7;
            *(uint4*)&sm[A_KHI + row * PA + c8 * 8] = *(const uint4*)(gk_hi + kbase + (size_t)row * DH + c8 * 8);
            *(uint4*)&sm[A_KLO + row * PA + c8 * 8] = *(const uint4*)(gk_lo + kbase + (size_t)row * DH + c8 * 8);
        }
        #pragma unroll
        for (int it = 0; it < 2; it++) {
            int c = it * 256 + tid;
            int row = c >> 3, c8 = c & 7;   // row = e
            size_t g = ((size_t)bh * DH + row) * S + kt * 64 + c8 * 8;
            *(uint4*)&sm[A_VHI + row * PA + c8 * 8] = *(const uint4*)(gvt_hi + g);
            *(uint4*)&sm[A_VLO + row * PA + c8 * 8] = *(const uint4*)(gvt_lo + g);
        }
        __syncthreads();

        // ---- S = Q K^T (split) ----
        float sc[8][4];
        #pragma unroll
        for (int nt = 0; nt < 8; nt++)
            #pragma unroll
            for (int v = 0; v < 4; v++) sc[nt][v] = 0.f;

        #pragma unroll
        for (int ks = 0; ks < 4; ks++) {
            uint32_t ah[4], al[4];
            uint32_t aoff = (uint32_t)((base_m + a_row_l) * PA + ks * 16 + a_col_l) * 2;
            LDSM_X4(ah[0], ah[1], ah[2], ah[3], smb + A_QHI * 2 + aoff);
            LDSM_X4(al[0], al[1], al[2], al[3], smb + A_QLO * 2 + aoff);
            #pragma unroll
            for (int nt = 0; nt < 8; nt++) {
                uint32_t bhf[2], blf[2];
                uint32_t boff = (uint32_t)((nt * 8 + b_row_l) * PA + ks * 16 + b_col_l) * 2;
                LDSM_X2(bhf[0], bhf[1], smb + A_KHI * 2 + boff);
                LDSM_X2(blf[0], blf[1], smb + A_KLO * 2 + boff);
                mma_bf16(sc[nt], ah, bhf);
                mma_bf16(sc[nt], ah, blf);
                mma_bf16(sc[nt], al, bhf);
            }
        }

        // ---- streaming softmax (rows: lane>>2 and +8) ----
        #pragma unroll
        for (int half = 0; half < 2; half++) {
            const int ci = half * 2;
            float mx = -INFINITY;
            #pragma unroll
            for (int nt = 0; nt < 8; nt++)
                mx = fmaxf(mx, fmaxf(sc[nt][ci], sc[nt][ci + 1]));
            mx = fmaxf(mx, __shfl_xor_sync(0xffffffffu, mx, 1));
            mx = fmaxf(mx, __shfl_xor_sync(0xffffffffu, mx, 2));
            float mnew = fmaxf(mrow[half], mx);
            float f = __expf(mrow[half] - mnew);
            mrow[half] = mnew;
            float rs = 0.f;
            #pragma unroll
            for (int nt = 0; nt < 8; nt++) {
                sc[nt][ci]     = __expf(sc[nt][ci]     - mnew);
                sc[nt][ci + 1] = __expf(sc[nt][ci + 1] - mnew);
                rs += sc[nt][ci] + sc[nt][ci + 1];
            }
            rs += __shfl_xor_sync(0xffffffffu, rs, 1);
            rs += __shfl_xor_sync(0xffffffffu, rs, 2);
            lrow[half] = lrow[half] * f + rs;
            #pragma unroll
            for (int nt = 0; nt < 8; nt++) {
                o[nt][ci] *= f;
                o[nt][ci + 1] *= f;
            }
        }

        // ---- pack P fragments (C->A identity) as split bf16 ----
        uint32_t pa_hi[4][4], pa_lo[4][4];
        #pragma unroll
        for (int ks = 0; ks < 4; ks++) {
            #pragma unroll
            for (int q = 0; q < 4; q++) {
                int nt = 2 * ks + (q >> 1);
                int pr = (q & 1) * 2;
                float p0 = sc[nt][pr], p1 = sc[nt][pr + 1];
                __nv_bfloat16 h0, l0, h1, l1;
                split2(p0, h0, l0); split2(p1, h1, l1);
                __nv_bfloat162 th; th.x = h0; th.y = h1;
                __nv_bfloat162 tl; tl.x = l0; tl.y = l1;
                pa_hi[ks][q] = *(uint32_t*)&th;
                pa_lo[ks][q] = *(uint32_t*)&tl;
            }
        }

        // ---- O += P V (split) ----
        #pragma unroll
        for (int ks = 0; ks < 4; ks++) {
            #pragma unroll
            for (int nt = 0; nt < 8; nt++) {
                uint32_t bhf[2], blf[2];
                uint32_t boff = (uint32_t)((nt * 8 + b_row_l) * PA + ks * 16 + b_col_l) * 2;
                LDSM_X2(bhf[0], bhf[1], smb + A_VHI * 2 + boff);
                LDSM_X2(blf[0], blf[1], smb + A_VLO * 2 + boff);
                mma_bf16(o[nt], pa_hi[ks], bhf);
                mma_bf16(o[nt], pa_hi[ks], blf);
                mma_bf16(o[nt], pa_lo[ks], bhf);
            }
        }
        __syncthreads();
    }

    // ---- epilogue: normalize, split, write heads ----
    const float inv0 = 1.f / lrow[0];
    const float inv1 = 1.f / lrow[1];
    const int b = bh >> 4, h = bh & 15;
    const int s0 = qt * 128 + base_m + (lane >> 2);
    const size_t tok0 = (size_t)b * S + s0;
    const size_t tok1 = tok0 + 8;
    #pragma unroll
    for (int nt = 0; nt < 8; nt++) {
        int col = h * DH + nt * 8 + (lane & 3) * 2;
        float v00 = o[nt][0] * inv0, v01 = o[nt][1] * inv0;
        float v10 = o[nt][2] * inv1, v11 = o[nt][3] * inv1;
        __nv_bfloat16 h0, l0, h1, l1;
        split2(v00, h0, l0); split2(v01, h1, l1);
        __nv_bfloat162 th; th.x = h0; th.y = h1;
        __nv_bfloat162 tl; tl.x = l0; tl.y = l1;
        *(__nv_bfloat162*)&gh_hi[tok0 * DM + col] = th;
        *(__nv_bfloat162*)&gh_lo[tok0 * DM + col] = tl;
        split2(v10, h0, l0); split2(v11, h1, l1);
        th.x = h0; th.y = h1; tl.x = l0; tl.y = l1;
        *(__nv_bfloat162*)&gh_hi[tok1 * DM + col] = th;
        *(__nv_bfloat162*)&gh_lo[tok1 * DM + col] = tl;
    }
}

// ---------------------------------------------------------------------------
extern "C" void kernel_launch(void* const* d_in, const int* in_sizes, int n_in,
                              void* d_out, int out_size)
{
    const float* x  = (const float*)d_in[0];
    const float* Wq = (const float*)d_in[1];
    const float* bq = (const float*)d_in[2];
    const float* Wk = (const float*)d_in[3];
    const float* bk = (const float*)d_in[4];
    const float* Wv = (const float*)d_in[5];
    const float* bv = (const float*)d_in[6];
    const float* Wo = (const float*)d_in[7];
    const float* bo = (const float*)d_in[8];
    float* out = (float*)d_out;

    static __nv_bfloat16 *p_gxh, *p_gxl, *p_gwh, *p_gwl, *p_gwoh, *p_gwol;
    static bool init = false;
    if (!init) {
        cudaGetSymbolAddress((void**)&p_gxh,  gx_hi);
        cudaGetSymbolAddress((void**)&p_gxl,  gx_lo);
        cudaGetSymbolAddress((void**)&p_gwh,  gw_hi);
        cudaGetSymbolAddress((void**)&p_gwl,  gw_lo);
        cudaGetSymbolAddress((void**)&p_gwoh, gwo_hi);
        cudaGetSymbolAddress((void**)&p_gwol, gwo_lo);
        cudaFuncSetAttribute(gemm_qkv_tc, cudaFuncAttributeMaxDynamicSharedMemorySize, GSM_BYTES);
        cudaFuncSetAttribute(gemm_out_tc, cudaFuncAttributeMaxDynamicSharedMemorySize, GSM_BYTES);
        cudaFuncSetAttribute(attn_mma,    cudaFuncAttributeMaxDynamicSharedMemorySize, ATT_BYTES);
        init = true;
    }

    // 1. split inputs to bf16 hi/lo
    split_kernel<<<(NTOK * DM / 4) / 256, 256>>>(x, p_gxh, p_gxl);
    tsplit_kernel<<<dim3(DH, H), 256>>>(Wq, p_gwh,                     p_gwl,                     DM, DH);
    tsplit_kernel<<<dim3(DH, H), 256>>>(Wk, p_gwh + (size_t)H*DH*DM,   p_gwl + (size_t)H*DH*DM,   DM, DH);
    tsplit_kernel<<<dim3(DH, H), 256>>>(Wv, p_gwh + (size_t)2*H*DH*DM, p_gwl + (size_t)2*H*DH*DM, DM, DH);
    tsplit_kernel<<<dim3(DM, 1), 256>>>(Wo, p_gwoh, p_gwol, DM, DM);

    // 2. QKV projection (HMMA) -> split Q(scaled)/K/V^T
    gemm_qkv_tc<<<dim3(64, 48), 256, GSM_BYTES>>>(bq, bk, bv);

    // 3. attention (HMMA, split)
    attn_mma<<<dim3(16, 64), 256, ATT_BYTES>>>();

    // 4. output projection (HMMA)
    gemm_out_tc<<<dim3(64, 16), 256, GSM_BYTES>>>(bo, out);
}

// round 5
// speedup vs baseline: 2.6108x; 1.1318x over previous
#include <cuda_runtime.h>
#include <cuda_bf16.h>
#include <math.h>
#include <cstdint>

#define B 4
#define H 16
#define S 2048
#define DM 1024
#define DH 64
#define SCALE 0.125f
#define NTOK (B*S)   // 8192

// ---------------------------------------------------------------------------
// Scratch (device globals: no allocations allowed)
// ---------------------------------------------------------------------------
__device__ __nv_bfloat16 gx_hi[(size_t)NTOK*DM], gx_lo[(size_t)NTOK*DM];
__device__ __nv_bfloat16 gw_hi[(size_t)3*H*DH*DM], gw_lo[(size_t)3*H*DH*DM];  // [(which*16+h)*64+e][d]
__device__ __nv_bfloat16 gwo_hi[(size_t)DM*DM], gwo_lo[(size_t)DM*DM];        // [n][k]
__device__ __nv_bfloat16 gh_hi[(size_t)NTOK*DM], gh_lo[(size_t)NTOK*DM];      // heads (attn out)

__device__ __nv_bfloat16 gq_hi[(size_t)B*H*S*DH], gq_lo[(size_t)B*H*S*DH];    // [bh][s][e], pre-scaled
__device__ __nv_bfloat16 gk_hi[(size_t)B*H*S*DH], gk_lo[(size_t)B*H*S*DH];    // [bh][s][e]
__device__ __nv_bfloat16 gvt_hi[(size_t)B*H*DH*S], gvt_lo[(size_t)B*H*DH*S];  // [bh][e][s]

// ---------------------------------------------------------------------------
// PTX helpers (sm_80-level, valid under compute_103)
// ---------------------------------------------------------------------------
__device__ __forceinline__ uint32_t smem_u32(const void* p) {
    uint32_t a;
    asm("{ .reg .u64 t; cvta.to.shared.u64 t, %1; cvt.u32.u64 %0, t; }" : "=r"(a) : "l"(p));
    return a;
}

#define LDSM_X4(r0, r1, r2, r3, addr) \
    asm volatile("ldmatrix.sync.aligned.m8n8.x4.shared.b16 {%0,%1,%2,%3}, [%4];" \
                 : "=r"(r0), "=r"(r1), "=r"(r2), "=r"(r3) : "r"(addr))

__device__ __forceinline__ void mma_bf16(float* c, const uint32_t* a, const uint32_t* b) {
    asm volatile("mma.sync.aligned.m16n8k16.row.col.f32.bf16.bf16.f32 "
                 "{%0,%1,%2,%3}, {%4,%5,%6,%7}, {%8,%9}, {%0,%1,%2,%3};"
                 : "+f"(c[0]), "+f"(c[1]), "+f"(c[2]), "+f"(c[3])
                 : "r"(a[0]), "r"(a[1]), "r"(a[2]), "r"(a[3]), "r"(b[0]), "r"(b[1]));
}

#define CP_ASYNC16(dst_u32, src_ptr) \
    asm volatile("cp.async.ca.shared.global [%0], [%1], 16;" \
                 :: "r"(dst_u32), "l"(src_ptr) : "memory")
#define CP_COMMIT() asm volatile("cp.async.commit_group;" ::: "memory")
#define CP_WAIT(n)  asm volatile("cp.async.wait_group %0;" :: "n"(n) : "memory")

// ---------------------------------------------------------------------------
// Split helpers & conversion kernels
// ---------------------------------------------------------------------------
__device__ __forceinline__ void split2(float a, __nv_bfloat16& h, __nv_bfloat16& l) {
    h = __float2bfloat16(a);
    l = __float2bfloat16(a - __bfloat162float(h));
}

__global__ __launch_bounds__(256) void split_kernel(const float* __restrict__ src,
        __nv_bfloat16* __restrict__ hi, __nv_bfloat16* __restrict__ lo) {
    int i = blockIdx.x * 256 + threadIdx.x;
    float4 v = ((const float4*)src)[i];
    __nv_bfloat16 h0,h1,h2,h3,l0,l1,l2,l3;
    split2(v.x,h0,l0); split2(v.y,h1,l1); split2(v.z,h2,l2); split2(v.w,h3,l3);
    __nv_bfloat162* hp = (__nv_bfloat162*)hi;
    __nv_bfloat162* lp = (__nv_bfloat162*)lo;
    __nv_bfloat162 t;
    t.x=h0; t.y=h1; hp[2*i]   = t;
    t.x=h2; t.y=h3; hp[2*i+1] = t;
    t.x=l0; t.y=l1; lp[2*i]   = t;
    t.x=l2; t.y=l3; lp[2*i+1] = t;
}

__global__ __launch_bounds__(256) void tsplit_kernel(const float* __restrict__ src,
        __nv_bfloat16* __restrict__ hi, __nv_bfloat16* __restrict__ lo, int K, int N) {
    src += (size_t)blockIdx.y * K * N;
    size_t obase = ((size_t)blockIdx.y * N + blockIdx.x) * K;
    for (int k = threadIdx.x; k < K; k += 256) {
        float a = src[(size_t)k * N + blockIdx.x];
        __nv_bfloat16 h, l; split2(a, h, l);
        hi[obase + k] = h; lo[obase + k] = l;
    }
}

// ---------------------------------------------------------------------------
// HMMA GEMM core v2: 128(M) x 128(N) tile, cp.async double-buffered K-stages.
// A row-major [m][k], B rows [n][k]. split-bf16, fp32 acc.
// 8 warps, each 32(m) x 64(n) = 2 x 8 mma tiles.
// ---------------------------------------------------------------------------
#define PA 72
#define G_COMP (128 * PA)                 // halves per component (128 rows)
#define G_STAGE (4 * G_COMP)              // Ahi,Alo,Bhi,Blo
#define GSM_BYTES (2 * G_STAGE * 2)       // 147456 B

__device__ __forceinline__ void g_prefetch(
    uint32_t sb, int buf,
    const __nv_bfloat16* a_hi, const __nv_bfloat16* a_lo, size_t arow0,
    const __nv_bfloat16* b_hi, const __nv_bfloat16* b_lo, size_t brow0,
    int k0, int tid)
{
    uint32_t st = sb + (uint32_t)buf * G_STAGE * 2;
    #pragma unroll
    for (int it = 0; it < 4; it++) {
        int c = it * 256 + tid;
        int row = c >> 3, c8 = c & 7;
        uint32_t so = (uint32_t)(row * PA + c8 * 8) * 2;
        size_t ga = (arow0 + row) * (size_t)DM + k0 + c8 * 8;
        size_t gb = (brow0 + row) * (size_t)DM + k0 + c8 * 8;
        CP_ASYNC16(st + 0 * G_COMP * 2 + so, a_hi + ga);
        CP_ASYNC16(st + 1 * G_COMP * 2 + so, a_lo + ga);
        CP_ASYNC16(st + 2 * G_COMP * 2 + so, b_hi + gb);
        CP_ASYNC16(st + 3 * G_COMP * 2 + so, b_lo + gb);
    }
}

__device__ __forceinline__ void gemm_tile_mma(
    const __nv_bfloat16* __restrict__ a_hi, const __nv_bfloat16* __restrict__ a_lo, size_t arow0,
    const __nv_bfloat16* __restrict__ b_hi, const __nv_bfloat16* __restrict__ b_lo, size_t brow0,
    float acc[2][8][4])
{
    extern __shared__ __nv_bfloat16 sm[];
    const int tid = threadIdx.x;
    const int wid = tid >> 5, lane = tid & 31;
    const int mg = (wid >> 1) * 32;
    const int ng = (wid & 1) * 64;

    #pragma unroll
    for (int m = 0; m < 2; m++)
        #pragma unroll
        for (int n = 0; n < 8; n++)
            #pragma unroll
            for (int v = 0; v < 4; v++) acc[m][n][v] = 0.f;

    const uint32_t sb = smem_u32(sm);
    const int a_row_l = (lane & 15);
    const int a_col_l = ((lane >> 4) << 3);
    const int b_row_l = ((lane >> 4) << 3) + (lane & 7);
    const int b_col_l = (((lane >> 3) & 1) << 3);

    g_prefetch(sb, 0, a_hi, a_lo, arow0, b_hi, b_lo, brow0, 0, tid);
    CP_COMMIT();

    for (int s = 0; s < 16; s++) {
        const int buf = s & 1;
        if (s + 1 < 16) {
            g_prefetch(sb, buf ^ 1, a_hi, a_lo, arow0, b_hi, b_lo, brow0, (s + 1) * 64, tid);
            CP_COMMIT();
            CP_WAIT(1);
        } else {
            CP_WAIT(0);
        }
        __syncthreads();

        const uint32_t st = sb + (uint32_t)buf * G_STAGE * 2;
        #pragma unroll
        for (int ks = 0; ks < 4; ks++) {
            uint32_t ah[2][4], al[2][4];
            #pragma unroll
            for (int m = 0; m < 2; m++) {
                uint32_t off = (uint32_t)((mg + m * 16 + a_row_l) * PA + ks * 16 + a_col_l) * 2;
                LDSM_X4(ah[m][0], ah[m][1], ah[m][2], ah[m][3], st + 0 * G_COMP * 2 + off);
                LDSM_X4(al[m][0], al[m][1], al[m][2], al[m][3], st + 1 * G_COMP * 2 + off);
            }
            #pragma unroll
            for (int p = 0; p < 4; p++) {
                uint32_t off = (uint32_t)((ng + p * 16 + b_row_l) * PA + ks * 16 + b_col_l) * 2;
                uint32_t bh4[4], bl4[4];
                LDSM_X4(bh4[0], bh4[1], bh4[2], bh4[3], st + 2 * G_COMP * 2 + off);
                LDSM_X4(bl4[0], bl4[1], bl4[2], bl4[3], st + 3 * G_COMP * 2 + off);
                #pragma unroll
                for (int m = 0; m < 2; m++) {
                    mma_bf16(acc[m][2*p],   ah[m], bh4);
                    mma_bf16(acc[m][2*p],   ah[m], bl4);
                    mma_bf16(acc[m][2*p],   al[m], bh4);
                    mma_bf16(acc[m][2*p+1], ah[m], bh4 + 2);
                    mma_bf16(acc[m][2*p+1], ah[m], bl4 + 2);
                    mma_bf16(acc[m][2*p+1], al[m], bh4 + 2);
                }
            }
        }
        __syncthreads();
    }
}

// ---------------------------------------------------------------------------
// QKV GEMM: grid (64 mtiles, 24 ntiles of 128). Writes split Q(scaled)/K/V^T.
// ---------------------------------------------------------------------------
__global__ __launch_bounds__(256) void gemm_qkv_tc(
    const float* __restrict__ bq, const float* __restrict__ bk, const float* __restrict__ bv)
{
    const int mt = blockIdx.x, nt = blockIdx.y;
    const size_t arow0 = (size_t)mt * 128;
    const size_t brow0 = (size_t)nt * 128;

    float acc[2][8][4];
    gemm_tile_mma(gx_hi, gx_lo, arow0, gw_hi, gw_lo, brow0, acc);

    const int tid = threadIdx.x, wid = tid >> 5, lane = tid & 31;
    const int mg = (wid >> 1) * 32;
    const int gcol0 = nt * 128 + (wid & 1) * 64;
    const int which = gcol0 >> 10;
    const int h = (gcol0 & 1023) >> 6;
    const float* bias = (which == 0) ? bq : (which == 1) ? bk : bv;

    #pragma unroll
    for (int m = 0; m < 2; m++) {
        #pragma unroll
        for (int n8 = 0; n8 < 8; n8++) {
            #pragma unroll
            for (int half = 0; half < 2; half++) {
                int r = mg + m * 16 + (lane >> 2) + half * 8;
                int e = n8 * 8 + (lane & 3) * 2;
                size_t mrow = arow0 + r;
                int b = (int)(mrow / S), sidx = (int)(mrow % S);
                int bhidx = b * H + h;
                float v0 = acc[m][n8][half * 2 + 0] + bias[h * DH + e];
                float v1 = acc[m][n8][half * 2 + 1] + bias[h * DH + e + 1];
                if (which == 0) { v0 *= SCALE; v1 *= SCALE; }
                __nv_bfloat16 h0, l0, h1, l1;
                split2(v0, h0, l0); split2(v1, h1, l1);
                if (which == 2) {
                    size_t base = ((size_t)bhidx * DH + e) * S + sidx;
                    gvt_hi[base] = h0;     gvt_lo[base] = l0;
                    gvt_hi[base + S] = h1; gvt_lo[base + S] = l1;
                } else {
                    __nv_bfloat16* dh = (which == 0) ? gq_hi : gk_hi;
                    __nv_bfloat16* dl = (which == 0) ? gq_lo : gk_lo;
                    size_t base = ((size_t)bhidx * S + sidx) * DH + e;
                    __nv_bfloat162 th; th.x = h0; th.y = h1;
                    __nv_bfloat162 tl; tl.x = l0; tl.y = l1;
                    *(__nv_bfloat162*)&dh[base] = th;
                    *(__nv_bfloat162*)&dl[base] = tl;
                }
            }
        }
    }
}

// ---------------------------------------------------------------------------
// Output GEMM: grid (64 mtiles, 8 ntiles of 128).
// ---------------------------------------------------------------------------
__global__ __launch_bounds__(256) void gemm_out_tc(const float* __restrict__ bo,
                                                   float* __restrict__ out)
{
    const int mt = blockIdx.x, nt = blockIdx.y;
    const size_t arow0 = (size_t)mt * 128;

    float acc[2][8][4];
    gemm_tile_mma(gh_hi, gh_lo, arow0, gwo_hi, gwo_lo, (size_t)nt * 128, acc);

    const int tid = threadIdx.x, wid = tid >> 5, lane = tid & 31;
    const int mg = (wid >> 1) * 32;
    const int gcol0 = nt * 128 + (wid & 1) * 64;

    #pragma unroll
    for (int m = 0; m < 2; m++) {
        #pragma unroll
        for (int n8 = 0; n8 < 8; n8++) {
            #pragma unroll
            for (int half = 0; half < 2; half++) {
                int r = mg + m * 16 + (lane >> 2) + half * 8;
                int c = gcol0 + n8 * 8 + (lane & 3) * 2;
                size_t mrow = arow0 + r;
                float2 w = {acc[m][n8][half * 2 + 0] + bo[c],
                            acc[m][n8][half * 2 + 1] + bo[c + 1]};
                *(float2*)&out[mrow * DM + c] = w;
            }
        }
    }
}

// ---------------------------------------------------------------------------
// Attention on HMMA (FA2, split-bf16 both MMAs), cp.async double-buffered KV.
// Block: 128 q rows x 1 (b,h). 8 warps, each 16 rows x all 64 cols.
// ---------------------------------------------------------------------------
#define A_QHI 0
#define A_QLO (128 * PA)
#define A_QREG (2 * 128 * PA)             // 18432 halves
#define A_KV_COMP (64 * PA)               // 4608 halves
#define A_KV_STAGE (4 * A_KV_COMP)        // Khi,Klo,Vhi,Vlo = 18432 halves
#define ATT_BYTES ((A_QREG + 2 * A_KV_STAGE) * 2)   // 110592 B

__device__ __forceinline__ void a_prefetch_kv(uint32_t sb, int buf, int bh, int kt, int tid)
{
    uint32_t st = sb + (uint32_t)(A_QREG + buf * A_KV_STAGE) * 2;
    #pragma unroll
    for (int it = 0; it < 2; it++) {
        int c = it * 256 + tid;
        int row = c >> 3, c8 = c & 7;
        uint32_t so = (uint32_t)(row * PA + c8 * 8) * 2;
        size_t gk = ((size_t)bh * S + kt * 64 + row) * DH + c8 * 8;
        size_t gv = ((size_t)bh * DH + row) * S + kt * 64 + c8 * 8;
        CP_ASYNC16(st + 0 * A_KV_COMP * 2 + so, gk_hi + gk);
        CP_ASYNC16(st + 1 * A_KV_COMP * 2 + so, gk_lo + gk);
        CP_ASYNC16(st + 2 * A_KV_COMP * 2 + so, gvt_hi + gv);
        CP_ASYNC16(st + 3 * A_KV_COMP * 2 + so, gvt_lo + gv);
    }
}

__global__ __launch_bounds__(256) void attn_mma()
{
    extern __shared__ __nv_bfloat16 sm[];
    const int qt = blockIdx.x;
    const int bh = blockIdx.y;
    const int tid = threadIdx.x, wid = tid >> 5, lane = tid & 31;
    const int base_m = wid * 16;
    const uint32_t sb = smem_u32(sm);
    const int a_row_l = (lane & 15);
    const int a_col_l = ((lane >> 4) << 3);
    const int b_row_l = ((lane >> 4) << 3) + (lane & 7);
    const int b_col_l = (((lane >> 3) & 1) << 3);

    // prefetch kv tile 0, then load Q synchronously
    a_prefetch_kv(sb, 0, bh, 0, tid);
    CP_COMMIT();

    const size_t qbase = ((size_t)bh * S + qt * 128) * DH;
    #pragma unroll
    for (int it = 0; it < 4; it++) {
        int c = it * 256 + tid;
        int row = c >> 3, c8 = c & 7;
        *(uint4*)&sm[A_QHI + row * PA + c8 * 8] = *(const uint4*)(gq_hi + qbase + (size_t)row * DH + c8 * 8);
        *(uint4*)&sm[A_QLO + row * PA + c8 * 8] = *(const uint4*)(gq_lo + qbase + (size_t)row * DH + c8 * 8);
    }

    float o[8][4];
    #pragma unroll
    for (int n = 0; n < 8; n++)
        #pragma unroll
        for (int v = 0; v < 4; v++) o[n][v] = 0.f;
    float mrow[2] = {-INFINITY, -INFINITY};
    float lrow[2] = {0.f, 0.f};

    for (int kt = 0; kt < S / 64; kt++) {
        const int buf = kt & 1;
        if (kt + 1 < S / 64) {
            a_prefetch_kv(sb, buf ^ 1, bh, kt + 1, tid);
            CP_COMMIT();
            CP_WAIT(1);
        } else {
            CP_WAIT(0);
        }
        __syncthreads();

        const uint32_t st = sb + (uint32_t)(A_QREG + buf * A_KV_STAGE) * 2;

        // ---- S = Q K^T (split) ----
        float sc[8][4];
        #pragma unroll
        for (int n = 0; n < 8; n++)
            #pragma unroll
            for (int v = 0; v < 4; v++) sc[n][v] = 0.f;

        #pragma unroll
        for (int ks = 0; ks < 4; ks++) {
            uint32_t ah[4], al[4];
            uint32_t aoff = (uint32_t)((base_m + a_row_l) * PA + ks * 16 + a_col_l) * 2;
            LDSM_X4(ah[0], ah[1], ah[2], ah[3], sb + A_QHI * 2 + aoff);
            LDSM_X4(al[0], al[1], al[2], al[3], sb + A_QLO * 2 + aoff);
            #pragma unroll
            for (int p = 0; p < 4; p++) {
                uint32_t boff = (uint32_t)((p * 16 + b_row_l) * PA + ks * 16 + b_col_l) * 2;
                uint32_t bh4[4], bl4[4];
                LDSM_X4(bh4[0], bh4[1], bh4[2], bh4[3], st + 0 * A_KV_COMP * 2 + boff);
                LDSM_X4(bl4[0], bl4[1], bl4[2], bl4[3], st + 1 * A_KV_COMP * 2 + boff);
                mma_bf16(sc[2*p],   ah, bh4);
                mma_bf16(sc[2*p],   ah, bl4);
                mma_bf16(sc[2*p],   al, bh4);
                mma_bf16(sc[2*p+1], ah, bh4 + 2);
                mma_bf16(sc[2*p+1], ah, bl4 + 2);
                mma_bf16(sc[2*p+1], al, bh4 + 2);
            }
        }

        // ---- streaming softmax ----
        #pragma unroll
        for (int half = 0; half < 2; half++) {
            const int ci = half * 2;
            float mx = -INFINITY;
            #pragma unroll
            for (int n = 0; n < 8; n++)
                mx = fmaxf(mx, fmaxf(sc[n][ci], sc[n][ci + 1]));
            mx = fmaxf(mx, __shfl_xor_sync(0xffffffffu, mx, 1));
            mx = fmaxf(mx, __shfl_xor_sync(0xffffffffu, mx, 2));
            float mnew = fmaxf(mrow[half], mx);
            float f = __expf(mrow[half] - mnew);
            mrow[half] = mnew;
            float rs = 0.f;
            #pragma unroll
            for (int n = 0; n < 8; n++) {
                sc[n][ci]     = __expf(sc[n][ci]     - mnew);
                sc[n][ci + 1] = __expf(sc[n][ci + 1] - mnew);
                rs += sc[n][ci] + sc[n][ci + 1];
            }
            rs += __shfl_xor_sync(0xffffffffu, rs, 1);
            rs += __shfl_xor_sync(0xffffffffu, rs, 2);
            lrow[half] = lrow[half] * f + rs;
            #pragma unroll
            for (int n = 0; n < 8; n++) {
                o[n][ci] *= f;
                o[n][ci + 1] *= f;
            }
        }

        // ---- pack P fragments (C->A identity), split bf16 ----
        uint32_t pa_hi[4][4], pa_lo[4][4];
        #pragma unroll
        for (int ks = 0; ks < 4; ks++) {
            #pragma unroll
            for (int q = 0; q < 4; q++) {
                int n = 2 * ks + (q >> 1);
                int pr = (q & 1) * 2;
                float p0 = sc[n][pr], p1 = sc[n][pr + 1];
                __nv_bfloat16 h0, l0, h1, l1;
                split2(p0, h0, l0); split2(p1, h1, l1);
                __nv_bfloat162 th; th.x = h0; th.y = h1;
                __nv_bfloat162 tl; tl.x = l0; tl.y = l1;
                pa_hi[ks][q] = *(uint32_t*)&th;
                pa_lo[ks][q] = *(uint32_t*)&tl;
            }
        }

        // ---- O += P V (split) ----
        #pragma unroll
        for (int ks = 0; ks < 4; ks++) {
            #pragma unroll
            for (int p = 0; p < 4; p++) {
                uint32_t boff = (uint32_t)((p * 16 + b_row_l) * PA + ks * 16 + b_col_l) * 2;
                uint32_t bh4[4], bl4[4];
                LDSM_X4(bh4[0], bh4[1], bh4[2], bh4[3], st + 2 * A_KV_COMP * 2 + boff);
                LDSM_X4(bl4[0], bl4[1], bl4[2], bl4[3], st + 3 * A_KV_COMP * 2 + boff);
                mma_bf16(o[2*p],   pa_hi[ks], bh4);
                mma_bf16(o[2*p],   pa_hi[ks], bl4);
                mma_bf16(o[2*p],   pa_lo[ks], bh4);
                mma_bf16(o[2*p+1], pa_hi[ks], bh4 + 2);
                mma_bf16(o[2*p+1], pa_hi[ks], bl4 + 2);
                mma_bf16(o[2*p+1], pa_lo[ks], bh4 + 2);
            }
        }
        __syncthreads();
    }

    // ---- epilogue ----
    const float inv0 = 1.f / lrow[0];
    const float inv1 = 1.f / lrow[1];
    const int b = bh >> 4, h = bh & 15;
    const int s0 = qt * 128 + base_m + (lane >> 2);
    const size_t tok0 = (size_t)b * S + s0;
    const size_t tok1 = tok0 + 8;
    #pragma unroll
    for (int n = 0; n < 8; n++) {
        int col = h * DH + n * 8 + (lane & 3) * 2;
        float v00 = o[n][0] * inv0, v01 = o[n][1] * inv0;
        float v10 = o[n][2] * inv1, v11 = o[n][3] * inv1;
        __nv_bfloat16 h0, l0, h1, l1;
        split2(v00, h0, l0); split2(v01, h1, l1);
        __nv_bfloat162 th; th.x = h0; th.y = h1;
        __nv_bfloat162 tl; tl.x = l0; tl.y = l1;
        *(__nv_bfloat162*)&gh_hi[tok0 * DM + col] = th;
        *(__nv_bfloat162*)&gh_lo[tok0 * DM + col] = tl;
        split2(v10, h0, l0); split2(v11, h1, l1);
        th.x = h0; th.y = h1; tl.x = l0; tl.y = l1;
        *(__nv_bfloat162*)&gh_hi[tok1 * DM + col] = th;
        *(__nv_bfloat162*)&gh_lo[tok1 * DM + col] = tl;
    }
}

// ---------------------------------------------------------------------------
extern "C" void kernel_launch(void* const* d_in, const int* in_sizes, int n_in,
                              void* d_out, int out_size)
{
    const float* x  = (const float*)d_in[0];
    const float* Wq = (const float*)d_in[1];
    const float* bq = (const float*)d_in[2];
    const float* Wk = (const float*)d_in[3];
    const float* bk = (const float*)d_in[4];
    const float* Wv = (const float*)d_in[5];
    const float* bv = (const float*)d_in[6];
    const float* Wo = (const float*)d_in[7];
    const float* bo = (const float*)d_in[8];
    float* out = (float*)d_out;

    static __nv_bfloat16 *p_gxh, *p_gxl, *p_gwh, *p_gwl, *p_gwoh, *p_gwol;
    static bool init = false;
    if (!init) {
        cudaGetSymbolAddress((void**)&p_gxh,  gx_hi);
        cudaGetSymbolAddress((void**)&p_gxl,  gx_lo);
        cudaGetSymbolAddress((void**)&p_gwh,  gw_hi);
        cudaGetSymbolAddress((void**)&p_gwl,  gw_lo);
        cudaGetSymbolAddress((void**)&p_gwoh, gwo_hi);
        cudaGetSymbolAddress((void**)&p_gwol, gwo_lo);
        cudaFuncSetAttribute(gemm_qkv_tc, cudaFuncAttributeMaxDynamicSharedMemorySize, GSM_BYTES);
        cudaFuncSetAttribute(gemm_out_tc, cudaFuncAttributeMaxDynamicSharedMemorySize, GSM_BYTES);
        cudaFuncSetAttribute(attn_mma,    cudaFuncAttributeMaxDynamicSharedMemorySize, ATT_BYTES);
        init = true;
    }

    // 1. split inputs to bf16 hi/lo
    split_kernel<<<(NTOK * DM / 4) / 256, 256>>>(x, p_gxh, p_gxl);
    tsplit_kernel<<<dim3(DH, H), 256>>>(Wq, p_gwh,                     p_gwl,                     DM, DH);
    tsplit_kernel<<<dim3(DH, H), 256>>>(Wk, p_gwh + (size_t)H*DH*DM,   p_gwl + (size_t)H*DH*DM,   DM, DH);
    tsplit_kernel<<<dim3(DH, H), 256>>>(Wv, p_gwh + (size_t)2*H*DH*DM, p_gwl + (size_t)2*H*DH*DM, DM, DH);
    tsplit_kernel<<<dim3(DM, 1), 256>>>(Wo, p_gwoh, p_gwol, DM, DM);

    // 2. QKV projection (HMMA, 128x128 tiles)
    gemm_qkv_tc<<<dim3(64, 24), 256, GSM_BYTES>>>(bq, bk, bv);

    // 3. attention (HMMA, split, cp.async pipelined)
    attn_mma<<<dim3(16, 64), 256, ATT_BYTES>>>();

    // 4. output projection (HMMA, 128x128 tiles)
    gemm_out_tc<<<dim3(64, 8), 256, GSM_BYTES>>>(bo, out);
}

// round 7
// speedup vs baseline: 3.7015x; 1.4177x over previous
#include <cuda_runtime.h>
#include <cuda_fp16.h>
#include <math.h>
#include <cstdint>

#define B 4
#define H 16
#define S 2048
#define DM 1024
#define DH 64
#define SCALE 0.125f
#define NTOK (B*S)   // 8192

// ---------------------------------------------------------------------------
// Scratch (device globals: no allocations allowed)
// A-side operands: hi only. B-side operands: hi+lo (fp16 2-term scheme).
// ---------------------------------------------------------------------------
__device__ __half gx[(size_t)NTOK*DM];                                    // x (A of qkv)
__device__ __half gw_hi[(size_t)3*H*DH*DM], gw_lo[(size_t)3*H*DH*DM];     // [(which*16+h)*64+e][d]
__device__ __half gwo_hi[(size_t)DM*DM], gwo_lo[(size_t)DM*DM];           // [n][k]
__device__ __half gh[(size_t)NTOK*DM];                                    // heads (A of out)

__device__ __half gq[(size_t)B*H*S*DH];                                   // [bh][s][e], pre-scaled (A of QK)
__device__ __half gk_hi[(size_t)B*H*S*DH], gk_lo[(size_t)B*H*S*DH];       // [bh][s][e]
__device__ __half gvt_hi[(size_t)B*H*DH*S], gvt_lo[(size_t)B*H*DH*S];     // [bh][e][s]

// ---------------------------------------------------------------------------
// PTX helpers (sm_80-level, valid under compute_103)
// ---------------------------------------------------------------------------
__device__ __forceinline__ uint32_t smem_u32(const void* p) {
    uint32_t a;
    asm("{ .reg .u64 t; cvta.to.shared.u64 t, %1; cvt.u32.u64 %0, t; }" : "=r"(a) : "l"(p));
    return a;
}

#define LDSM_X4(r0, r1, r2, r3, addr) \
    asm volatile("ldmatrix.sync.aligned.m8n8.x4.shared.b16 {%0,%1,%2,%3}, [%4];" \
                 : "=r"(r0), "=r"(r1), "=r"(r2), "=r"(r3) : "r"(addr))

__device__ __forceinline__ void mma_fp16(float* c, const uint32_t* a, const uint32_t* b) {
    asm volatile("mma.sync.aligned.m16n8k16.row.col.f32.f16.f16.f32 "
                 "{%0,%1,%2,%3}, {%4,%5,%6,%7}, {%8,%9}, {%0,%1,%2,%3};"
                 : "+f"(c[0]), "+f"(c[1]), "+f"(c[2]), "+f"(c[3])
                 : "r"(a[0]), "r"(a[1]), "r"(a[2]), "r"(a[3]), "r"(b[0]), "r"(b[1]));
}

#define CP_ASYNC16(dst_u32, src_ptr) \
    asm volatile("cp.async.ca.shared.global [%0], [%1], 16;" \
                 :: "r"(dst_u32), "l"(src_ptr) : "memory")
#define CP_COMMIT() asm volatile("cp.async.commit_group;" ::: "memory")
#define CP_WAIT(n)  asm volatile("cp.async.wait_group %0;" :: "n"(n) : "memory")

// ---------------------------------------------------------------------------
// Split helpers & conversion kernels
// ---------------------------------------------------------------------------
__device__ __forceinline__ void split2h(float a, __half& h, __half& l) {
    h = __float2half_rn(a);
    l = __float2half_rn(a - __half2float(h));
}

// plain fp16 convert (A-side)
__global__ __launch_bounds__(256) void cvt_kernel(const float* __restrict__ src,
                                                  __half* __restrict__ dst) {
    int i = blockIdx.x * 256 + threadIdx.x;   // one float4
    float4 v = ((const float4*)src)[i];
    __half2* dp = (__half2*)dst;
    dp[2*i]   = __floats2half2_rn(v.x, v.y);
    dp[2*i+1] = __floats2half2_rn(v.z, v.w);
}

// transpose + split (B-side): src [K,N] per blockIdx.y -> out[(y*N+n)*K+k] hi/lo
__global__ __launch_bounds__(256) void tsplit_kernel(const float* __restrict__ src,
        __half* __restrict__ hi, __half* __restrict__ lo, int K, int N) {
    src += (size_t)blockIdx.y * K * N;
    size_t obase = ((size_t)blockIdx.y * N + blockIdx.x) * K;
    for (int k = threadIdx.x; k < K; k += 256) {
        float a = src[(size_t)k * N + blockIdx.x];
        __half h, l; split2h(a, h, l);
        hi[obase + k] = h; lo[obase + k] = l;
    }
}

// ---------------------------------------------------------------------------
// GEMM core: 128(M) x 128(N), cp.async double-buffered 64-wide K-stages.
// A plain fp16 rows [m][k]; B split rows [n][k] hi/lo. fp32 acc.
// 8 warps, each 32(m) x 64(n). 2-term: acc += A*Bhi + A*Blo.
// ---------------------------------------------------------------------------
#define PA 72
#define G_COMP (128 * PA)                 // halves per component
#define G_STAGE (3 * G_COMP)              // A, Bhi, Blo
#define GSM_BYTES (2 * G_STAGE * 2)       // 110592 B

__device__ __forceinline__ void g_prefetch(
    uint32_t sb, int buf,
    const __half* a, size_t arow0,
    const __half* b_hi, const __half* b_lo, size_t brow0,
    int k0, int tid)
{
    uint32_t st = sb + (uint32_t)buf * G_STAGE * 2;
    #pragma unroll
    for (int it = 0; it < 4; it++) {
        int c = it * 256 + tid;
        int row = c >> 3, c8 = c & 7;
        uint32_t so = (uint32_t)(row * PA + c8 * 8) * 2;
        size_t ga = (arow0 + row) * (size_t)DM + k0 + c8 * 8;
        size_t gb = (brow0 + row) * (size_t)DM + k0 + c8 * 8;
        CP_ASYNC16(st + 0 * G_COMP * 2 + so, a + ga);
        CP_ASYNC16(st + 1 * G_COMP * 2 + so, b_hi + gb);
        CP_ASYNC16(st + 2 * G_COMP * 2 + so, b_lo + gb);
    }
}

__device__ __forceinline__ void gemm_tile_mma(
    const __half* __restrict__ a, size_t arow0,
    const __half* __restrict__ b_hi, const __half* __restrict__ b_lo, size_t brow0,
    float acc[2][8][4])
{
    extern __shared__ __half sm[];
    const int tid = threadIdx.x;
    const int wid = tid >> 5, lane = tid & 31;
    const int mg = (wid >> 1) * 32;
    const int ng = (wid & 1) * 64;

    #pragma unroll
    for (int m = 0; m < 2; m++)
        #pragma unroll
        for (int n = 0; n < 8; n++)
            #pragma unroll
            for (int v = 0; v < 4; v++) acc[m][n][v] = 0.f;

    const uint32_t sb = smem_u32(sm);
    const int a_row_l = (lane & 15);
    const int a_col_l = ((lane >> 4) << 3);
    const int b_row_l = ((lane >> 4) << 3) + (lane & 7);
    const int b_col_l = (((lane >> 3) & 1) << 3);

    g_prefetch(sb, 0, a, arow0, b_hi, b_lo, brow0, 0, tid);
    CP_COMMIT();

    for (int s = 0; s < 16; s++) {
        const int buf = s & 1;
        if (s + 1 < 16) {
            g_prefetch(sb, buf ^ 1, a, arow0, b_hi, b_lo, brow0, (s + 1) * 64, tid);
            CP_COMMIT();
            CP_WAIT(1);
        } else {
            CP_WAIT(0);
        }
        __syncthreads();

        const uint32_t st = sb + (uint32_t)buf * G_STAGE * 2;
        #pragma unroll
        for (int ks = 0; ks < 4; ks++) {
            uint32_t ar[2][4];
            #pragma unroll
            for (int m = 0; m < 2; m++) {
                uint32_t off = (uint32_t)((mg + m * 16 + a_row_l) * PA + ks * 16 + a_col_l) * 2;
                LDSM_X4(ar[m][0], ar[m][1], ar[m][2], ar[m][3], st + 0 * G_COMP * 2 + off);
            }
            #pragma unroll
            for (int p = 0; p < 4; p++) {
                uint32_t off = (uint32_t)((ng + p * 16 + b_row_l) * PA + ks * 16 + b_col_l) * 2;
                uint32_t bh4[4], bl4[4];
                LDSM_X4(bh4[0], bh4[1], bh4[2], bh4[3], st + 1 * G_COMP * 2 + off);
                LDSM_X4(bl4[0], bl4[1], bl4[2], bl4[3], st + 2 * G_COMP * 2 + off);
                #pragma unroll
                for (int m = 0; m < 2; m++) {
                    mma_fp16(acc[m][2*p],   ar[m], bh4);
                    mma_fp16(acc[m][2*p],   ar[m], bl4);
                    mma_fp16(acc[m][2*p+1], ar[m], bh4 + 2);
                    mma_fp16(acc[m][2*p+1], ar[m], bl4 + 2);
                }
            }
        }
        __syncthreads();
    }
}

// ---------------------------------------------------------------------------
// QKV GEMM: grid (64 mtiles, 24 ntiles of 128). Writes Q(fp16,scaled), K hi/lo, V^T hi/lo.
// ---------------------------------------------------------------------------
__global__ __launch_bounds__(256) void gemm_qkv_tc(
    const float* __restrict__ bq, const float* __restrict__ bk, const float* __restrict__ bv)
{
    const int mt = blockIdx.x, nt = blockIdx.y;
    const size_t arow0 = (size_t)mt * 128;
    const size_t brow0 = (size_t)nt * 128;

    float acc[2][8][4];
    gemm_tile_mma(gx, arow0, gw_hi, gw_lo, brow0, acc);

    const int tid = threadIdx.x, wid = tid >> 5, lane = tid & 31;
    const int mg = (wid >> 1) * 32;
    const int gcol0 = nt * 128 + (wid & 1) * 64;
    const int which = gcol0 >> 10;
    const int h = (gcol0 & 1023) >> 6;
    const float* bias = (which == 0) ? bq : (which == 1) ? bk : bv;

    #pragma unroll
    for (int m = 0; m < 2; m++) {
        #pragma unroll
        for (int n8 = 0; n8 < 8; n8++) {
            #pragma unroll
            for (int half_ = 0; half_ < 2; half_++) {
                int r = mg + m * 16 + (lane >> 2) + half_ * 8;
                int e = n8 * 8 + (lane & 3) * 2;
                size_t mrow = arow0 + r;
                int b = (int)(mrow / S), sidx = (int)(mrow % S);
                int bhidx = b * H + h;
                float v0 = acc[m][n8][half_ * 2 + 0] + bias[h * DH + e];
                float v1 = acc[m][n8][half_ * 2 + 1] + bias[h * DH + e + 1];
                if (which == 0) {
                    v0 *= SCALE; v1 *= SCALE;
                    size_t base = ((size_t)bhidx * S + sidx) * DH + e;
                    *(__half2*)&gq[base] = __floats2half2_rn(v0, v1);
                } else if (which == 1) {
                    __half h0, l0, h1, l1;
                    split2h(v0, h0, l0); split2h(v1, h1, l1);
                    size_t base = ((size_t)bhidx * S + sidx) * DH + e;
                    __half2 th; th.x = h0; th.y = h1;
                    __half2 tl; tl.x = l0; tl.y = l1;
                    *(__half2*)&gk_hi[base] = th;
                    *(__half2*)&gk_lo[base] = tl;
                } else {
                    __half h0, l0, h1, l1;
                    split2h(v0, h0, l0); split2h(v1, h1, l1);
                    size_t base = ((size_t)bhidx * DH + e) * S + sidx;
                    gvt_hi[base] = h0;     gvt_lo[base] = l0;
                    gvt_hi[base + S] = h1; gvt_lo[base + S] = l1;
                }
            }
        }
    }
}

// ---------------------------------------------------------------------------
// Output GEMM: grid (64 mtiles, 8 ntiles of 128).
// ---------------------------------------------------------------------------
__global__ __launch_bounds__(256) void gemm_out_tc(const float* __restrict__ bo,
                                                   float* __restrict__ out)
{
    const int mt = blockIdx.x, nt = blockIdx.y;
    const size_t arow0 = (size_t)mt * 128;

    float acc[2][8][4];
    gemm_tile_mma(gh, arow0, gwo_hi, gwo_lo, (size_t)nt * 128, acc);

    const int tid = threadIdx.x, wid = tid >> 5, lane = tid & 31;
    const int mg = (wid >> 1) * 32;
    const int gcol0 = nt * 128 + (wid & 1) * 64;

    #pragma unroll
    for (int m = 0; m < 2; m++) {
        #pragma unroll
        for (int n8 = 0; n8 < 8; n8++) {
            #pragma unroll
            for (int half_ = 0; half_ < 2; half_++) {
                int r = mg + m * 16 + (lane >> 2) + half_ * 8;
                int c = gcol0 + n8 * 8 + (lane & 3) * 2;
                size_t mrow = arow0 + r;
                float2 w = {acc[m][n8][half_ * 2 + 0] + bo[c],
                            acc[m][n8][half_ * 2 + 1] + bo[c + 1]};
                *(float2*)&out[mrow * DM + c] = w;
            }
        }
    }
}

// ---------------------------------------------------------------------------
// Attention (FA2, fp16 2-term both MMAs), cp.async double-buffered KV.
// Block: 128 q rows x 1 (b,h). 8 warps, each 16 rows x 64 cols.
// ---------------------------------------------------------------------------
#define A_Q 0                              // 128*PA halves (Q hi only)
#define A_KV0 (128 * PA)
#define A_KV_COMP (64 * PA)
#define A_KV_STAGE (4 * A_KV_COMP)         // Khi,Klo,Vhi,Vlo
#define ATT_BYTES ((128 * PA + 2 * A_KV_STAGE) * 2)   // 92160 B

__device__ __forceinline__ void a_prefetch_kv(uint32_t sb, int buf, int bh, int kt, int tid)
{
    uint32_t st = sb + (uint32_t)(A_KV0 + buf * A_KV_STAGE) * 2;
    #pragma unroll
    for (int it = 0; it < 2; it++) {
        int c = it * 256 + tid;
        int row = c >> 3, c8 = c & 7;
        uint32_t so = (uint32_t)(row * PA + c8 * 8) * 2;
        size_t gk = ((size_t)bh * S + kt * 64 + row) * DH + c8 * 8;
        size_t gv = ((size_t)bh * DH + row) * S + kt * 64 + c8 * 8;
        CP_ASYNC16(st + 0 * A_KV_COMP * 2 + so, gk_hi + gk);
        CP_ASYNC16(st + 1 * A_KV_COMP * 2 + so, gk_lo + gk);
        CP_ASYNC16(st + 2 * A_KV_COMP * 2 + so, gvt_hi + gv);
        CP_ASYNC16(st + 3 * A_KV_COMP * 2 + so, gvt_lo + gv);
    }
}

__global__ __launch_bounds__(256) void attn_mma()
{
    extern __shared__ __half sm[];
    const int qt = blockIdx.x;
    const int bh = blockIdx.y;
    const int tid = threadIdx.x, wid = tid >> 5, lane = tid & 31;
    const int base_m = wid * 16;
    const uint32_t sb = smem_u32(sm);
    const int a_row_l = (lane & 15);
    const int a_col_l = ((lane >> 4) << 3);
    const int b_row_l = ((lane >> 4) << 3) + (lane & 7);
    const int b_col_l = (((lane >> 3) & 1) << 3);

    a_prefetch_kv(sb, 0, bh, 0, tid);
    CP_COMMIT();

    const size_t qbase = ((size_t)bh * S + qt * 128) * DH;
    #pragma unroll
    for (int it = 0; it < 4; it++) {
        int c = it * 256 + tid;
        int row = c >> 3, c8 = c & 7;
        *(uint4*)&sm[A_Q + row * PA + c8 * 8] = *(const uint4*)(gq + qbase + (size_t)row * DH + c8 * 8);
    }

    float o[8][4];
    #pragma unroll
    for (int n = 0; n < 8; n++)
        #pragma unroll
        for (int v = 0; v < 4; v++) o[n][v] = 0.f;
    float mrow[2] = {-INFINITY, -INFINITY};
    float lrow[2] = {0.f, 0.f};

    for (int kt = 0; kt < S / 64; kt++) {
        const int buf = kt & 1;
        if (kt + 1 < S / 64) {
            a_prefetch_kv(sb, buf ^ 1, bh, kt + 1, tid);
            CP_COMMIT();
            CP_WAIT(1);
        } else {
            CP_WAIT(0);
        }
        __syncthreads();

        const uint32_t st = sb + (uint32_t)(A_KV0 + buf * A_KV_STAGE) * 2;

        // ---- S = Q K^T (2-term) ----
        float sc[8][4];
        #pragma unroll
        for (int n = 0; n < 8; n++)
            #pragma unroll
            for (int v = 0; v < 4; v++) sc[n][v] = 0.f;

        #pragma unroll
        for (int ks = 0; ks < 4; ks++) {
            uint32_t ar[4];
            uint32_t aoff = (uint32_t)((base_m + a_row_l) * PA + ks * 16 + a_col_l) * 2;
            LDSM_X4(ar[0], ar[1], ar[2], ar[3], sb + A_Q * 2 + aoff);
            #pragma unroll
            for (int p = 0; p < 4; p++) {
                uint32_t boff = (uint32_t)((p * 16 + b_row_l) * PA + ks * 16 + b_col_l) * 2;
                uint32_t kh4[4], kl4[4];
                LDSM_X4(kh4[0], kh4[1], kh4[2], kh4[3], st + 0 * A_KV_COMP * 2 + boff);
                LDSM_X4(kl4[0], kl4[1], kl4[2], kl4[3], st + 1 * A_KV_COMP * 2 + boff);
                mma_fp16(sc[2*p],   ar, kh4);
                mma_fp16(sc[2*p],   ar, kl4);
                mma_fp16(sc[2*p+1], ar, kh4 + 2);
                mma_fp16(sc[2*p+1], ar, kl4 + 2);
            }
        }

        // ---- streaming softmax ----
        #pragma unroll
        for (int half_ = 0; half_ < 2; half_++) {
            const int ci = half_ * 2;
            float mx = -INFINITY;
            #pragma unroll
            for (int n = 0; n < 8; n++)
                mx = fmaxf(mx, fmaxf(sc[n][ci], sc[n][ci + 1]));
            mx = fmaxf(mx, __shfl_xor_sync(0xffffffffu, mx, 1));
            mx = fmaxf(mx, __shfl_xor_sync(0xffffffffu, mx, 2));
            float mnew = fmaxf(mrow[half_], mx);
            float f = __expf(mrow[half_] - mnew);
            mrow[half_] = mnew;
            float rs = 0.f;
            #pragma unroll
            for (int n = 0; n < 8; n++) {
                sc[n][ci]     = __expf(sc[n][ci]     - mnew);
                sc[n][ci + 1] = __expf(sc[n][ci + 1] - mnew);
                rs += sc[n][ci] + sc[n][ci + 1];
            }
            rs += __shfl_xor_sync(0xffffffffu, rs, 1);
            rs += __shfl_xor_sync(0xffffffffu, rs, 2);
            lrow[half_] = lrow[half_] * f + rs;
            #pragma unroll
            for (int n = 0; n < 8; n++) {
                o[n][ci] *= f;
                o[n][ci + 1] *= f;
            }
        }

        // ---- pack P fragments (C->A identity), plain fp16 ----
        uint32_t pa[4][4];
        #pragma unroll
        for (int ks = 0; ks < 4; ks++) {
            #pragma unroll
            for (int q = 0; q < 4; q++) {
                int n = 2 * ks + (q >> 1);
                int pr = (q & 1) * 2;
                __half2 t = __floats2half2_rn(sc[n][pr], sc[n][pr + 1]);
                pa[ks][q] = *(uint32_t*)&t;
            }
        }

        // ---- O += P V (2-term) ----
        #pragma unroll
        for (int ks = 0; ks < 4; ks++) {
            #pragma unroll
            for (int p = 0; p < 4; p++) {
                uint32_t boff = (uint32_t)((p * 16 + b_row_l) * PA + ks * 16 + b_col_l) * 2;
                uint32_t vh4[4], vl4[4];
                LDSM_X4(vh4[0], vh4[1], vh4[2], vh4[3], st + 2 * A_KV_COMP * 2 + boff);
                LDSM_X4(vl4[0], vl4[1], vl4[2], vl4[3], st + 3 * A_KV_COMP * 2 + boff);
                mma_fp16(o[2*p],   pa[ks], vh4);
                mma_fp16(o[2*p],   pa[ks], vl4);
                mma_fp16(o[2*p+1], pa[ks], vh4 + 2);
                mma_fp16(o[2*p+1], pa[ks], vl4 + 2);
            }
        }
        __syncthreads();
    }

    // ---- epilogue: normalize, write heads (fp16 hi only) ----
    const float inv0 = 1.f / lrow[0];
    const float inv1 = 1.f / lrow[1];
    const int b = bh >> 4, h = bh & 15;
    const int s0 = qt * 128 + base_m + (lane >> 2);
    const size_t tok0 = (size_t)b * S + s0;
    const size_t tok1 = tok0 + 8;
    #pragma unroll
    for (int n = 0; n < 8; n++) {
        int col = h * DH + n * 8 + (lane & 3) * 2;
        *(__half2*)&gh[tok0 * DM + col] = __floats2half2_rn(o[n][0] * inv0, o[n][1] * inv0);
        *(__half2*)&gh[tok1 * DM + col] = __floats2half2_rn(o[n][2] * inv1, o[n][3] * inv1);
    }
}

// ---------------------------------------------------------------------------
extern "C" void kernel_launch(void* const* d_in, const int* in_sizes, int n_in,
                              void* d_out, int out_size)
{
    const float* x  = (const float*)d_in[0];
    const float* Wq = (const float*)d_in[1];
    const float* bq = (const float*)d_in[2];
    const float* Wk = (const float*)d_in[3];
    const float* bk = (const float*)d_in[4];
    const float* Wv = (const float*)d_in[5];
    const float* bv = (const float*)d_in[6];
    const float* Wo = (const float*)d_in[7];
    const float* bo = (const float*)d_in[8];
    float* out = (float*)d_out;

    static __half *p_gx, *p_gwh, *p_gwl, *p_gwoh, *p_gwol;
    static bool init = false;
    if (!init) {
        cudaGetSymbolAddress((void**)&p_gx,   gx);
        cudaGetSymbolAddress((void**)&p_gwh,  gw_hi);
        cudaGetSymbolAddress((void**)&p_gwl,  gw_lo);
        cudaGetSymbolAddress((void**)&p_gwoh, gwo_hi);
        cudaGetSymbolAddress((void**)&p_gwol, gwo_lo);
        cudaFuncSetAttribute(gemm_qkv_tc, cudaFuncAttributeMaxDynamicSharedMemorySize, GSM_BYTES);
        cudaFuncSetAttribute(gemm_out_tc, cudaFuncAttributeMaxDynamicSharedMemorySize, GSM_BYTES);
        cudaFuncSetAttribute(attn_mma,    cudaFuncAttributeMaxDynamicSharedMemorySize, ATT_BYTES);
        init = true;
    }

    // 1. convert/split inputs
    cvt_kernel<<<(NTOK * DM / 4) / 256, 256>>>(x, p_gx);
    tsplit_kernel<<<dim3(DH, H), 256>>>(Wq, p_gwh,                     p_gwl,                     DM, DH);
    tsplit_kernel<<<dim3(DH, H), 256>>>(Wk, p_gwh + (size_t)H*DH*DM,   p_gwl + (size_t)H*DH*DM,   DM, DH);
    tsplit_kernel<<<dim3(DH, H), 256>>>(Wv, p_gwh + (size_t)2*H*DH*DM, p_gwl + (size_t)2*H*DH*DM, DM, DH);
    tsplit_kernel<<<dim3(DM, 1), 256>>>(Wo, p_gwoh, p_gwol, DM, DM);

    // 2. QKV projection (fp16 2-term HMMA)
    gemm_qkv_tc<<<dim3(64, 24), 256, GSM_BYTES>>>(bq, bk, bv);

    // 3. attention (fp16 2-term HMMA, cp.async pipelined)
    attn_mma<<<dim3(16, 64), 256, ATT_BYTES>>>();

    // 4. output projection (fp16 2-term HMMA)
    gemm_out_tc<<<dim3(64, 8), 256, GSM_BYTES>>>(bo, out);
}

// round 8
// speedup vs baseline: 3.8751x; 1.0469x over previous
#include <cuda_runtime.h>
#include <cuda_fp16.h>
#include <math.h>
#include <cstdint>

#define B 4
#define H 16
#define S 2048
#define DM 1024
#define DH 64
#define SCALE 0.125f
#define NTOK (B*S)   // 8192

// ---------------------------------------------------------------------------
// Scratch (device globals: no allocations allowed)
// A-side operands: hi only. B-side operands: hi+lo (fp16 2-term scheme).
// ---------------------------------------------------------------------------
__device__ __half gx[(size_t)NTOK*DM];                                    // x (A of qkv)
__device__ __half gw_hi[(size_t)3*H*DH*DM], gw_lo[(size_t)3*H*DH*DM];     // [(which*16+h)*64+e][d]
__device__ __half gwo_hi[(size_t)DM*DM], gwo_lo[(size_t)DM*DM];           // [n][k]
__device__ __half gh[(size_t)NTOK*DM];                                    // heads (A of out)

__device__ __half gq[(size_t)B*H*S*DH];                                   // [bh][s][e], pre-scaled
__device__ __half gk_hi[(size_t)B*H*S*DH], gk_lo[(size_t)B*H*S*DH];       // [bh][s][e]
__device__ __half gvt_hi[(size_t)B*H*DH*S], gvt_lo[(size_t)B*H*DH*S];     // [bh][e][s]

// ---------------------------------------------------------------------------
// PTX helpers (sm_80-level, valid under compute_103)
// ---------------------------------------------------------------------------
__device__ __forceinline__ uint32_t smem_u32(const void* p) {
    uint32_t a;
    asm("{ .reg .u64 t; cvta.to.shared.u64 t, %1; cvt.u32.u64 %0, t; }" : "=r"(a) : "l"(p));
    return a;
}

#define LDSM_X4(r0, r1, r2, r3, addr) \
    asm volatile("ldmatrix.sync.aligned.m8n8.x4.shared.b16 {%0,%1,%2,%3}, [%4];" \
                 : "=r"(r0), "=r"(r1), "=r"(r2), "=r"(r3) : "r"(addr))

__device__ __forceinline__ void mma_fp16(float* c, const uint32_t* a, const uint32_t* b) {
    asm volatile("mma.sync.aligned.m16n8k16.row.col.f32.f16.f16.f32 "
                 "{%0,%1,%2,%3}, {%4,%5,%6,%7}, {%8,%9}, {%0,%1,%2,%3};"
                 : "+f"(c[0]), "+f"(c[1]), "+f"(c[2]), "+f"(c[3])
                 : "r"(a[0]), "r"(a[1]), "r"(a[2]), "r"(a[3]), "r"(b[0]), "r"(b[1]));
}

#define CP_ASYNC16(dst_u32, src_ptr) \
    asm volatile("cp.async.ca.shared.global [%0], [%1], 16;" \
                 :: "r"(dst_u32), "l"(src_ptr) : "memory")
#define CP_COMMIT() asm volatile("cp.async.commit_group;" ::: "memory")
#define CP_WAIT(n)  asm volatile("cp.async.wait_group %0;" :: "n"(n) : "memory")

__device__ __forceinline__ void split2h(float a, __half& h, __half& l) {
    h = __float2half_rn(a);
    l = __float2half_rn(a - __half2float(h));
}

// ---------------------------------------------------------------------------
// Fused prep: x->fp16, W q/k/v transpose+split, Wo transpose+split. 1 launch.
// grid = 2048 (x) + 3*1024 (W tiles) + 1024 (Wo tiles) = 6144 blocks, 256 thr.
// ---------------------------------------------------------------------------
__global__ __launch_bounds__(256) void prep_kernel(
    const float* __restrict__ x,
    const float* __restrict__ Wq, const float* __restrict__ Wk, const float* __restrict__ Wv,
    const float* __restrict__ Wo)
{
    const int bid = blockIdx.x;
    const int tid = threadIdx.x;

    if (bid < 2048) {
        // x convert: 2048 blocks * 256 thr * 4 float4
        __half2* dp = (__half2*)gx;
        #pragma unroll
        for (int j = 0; j < 4; j++) {
            int i = bid * 1024 + j * 256 + tid;
            float4 v = ((const float4*)x)[i];
            dp[2*i]   = __floats2half2_rn(v.x, v.y);
            dp[2*i+1] = __floats2half2_rn(v.z, v.w);
        }
        return;
    }

    __shared__ float tile[32][33];
    const int t = bid - 2048;
    const float* src;
    __half *dst_hi, *dst_lo;
    int d0, e0, in_stride, out_stride;
    size_t in_base, out_base;

    if (t < 3072) {
        // W job: [h: 1024 rows(d) x 64 cols(e)] -> out[(which*16+h)*64+e][d]
        const int which = t >> 10;
        const int r = t & 1023;
        const int h = r >> 6;
        const int tl = r & 63;
        const int tk = tl >> 1, te = tl & 1;
        src = (which == 0) ? Wq : (which == 1) ? Wk : Wv;
        d0 = tk * 32; e0 = te * 32;
        in_stride = DH; out_stride = DM;
        in_base  = (size_t)h * DM * DH;
        out_base = ((size_t)(which * H + h) * DH) * DM;
        dst_hi = gw_hi; dst_lo = gw_lo;
    } else {
        // Wo job: [1024(k) x 1024(n)] -> out[n][k]
        const int t2 = t - 3072;
        d0 = (t2 >> 5) * 32; e0 = (t2 & 31) * 32;
        src = Wo; in_stride = DM; out_stride = DM;
        in_base = 0; out_base = 0;
        dst_hi = gwo_hi; dst_lo = gwo_lo;
    }

    const int tx = tid & 31, ty = tid >> 5;   // 8 rows per pass
    #pragma unroll
    for (int p = 0; p < 4; p++) {
        int row = ty + p * 8;
        tile[row][tx] = src[in_base + (size_t)(d0 + row) * in_stride + e0 + tx];
    }
    __syncthreads();
    #pragma unroll
    for (int p = 0; p < 4; p++) {
        int erow = ty + p * 8;
        float v = tile[tx][erow];
        __half h, l; split2h(v, h, l);
        size_t oi = out_base + (size_t)(e0 + erow) * out_stride + d0 + tx;
        dst_hi[oi] = h; dst_lo[oi] = l;
    }
}

// ---------------------------------------------------------------------------
// GEMM core v3: 256(M) x 128(N) tile, 512 threads (16 warps, warp 64x32),
// cp.async double-buffered 64-wide K stages. 2-term: acc += A*Bhi + A*Blo.
// ---------------------------------------------------------------------------
#define PA 72
#define G_A 0
#define G_BHI (256 * PA)
#define G_BLO (256 * PA + 128 * PA)
#define G_STAGE (512 * PA)                // halves
#define GSM_BYTES (2 * G_STAGE * 2)       // 147456 B

__device__ __forceinline__ void g_prefetch(
    uint32_t sb, int buf,
    const __half* a, size_t arow0,
    const __half* b_hi, const __half* b_lo, size_t brow0,
    int k0, int tid)
{
    uint32_t st = sb + (uint32_t)buf * G_STAGE * 2;
    #pragma unroll
    for (int it = 0; it < 4; it++) {          // A: 256 rows x 8 chunks
        int c = it * 512 + tid;
        int row = c >> 3, c8 = c & 7;
        uint32_t so = (uint32_t)(row * PA + c8 * 8) * 2;
        CP_ASYNC16(st + G_A * 2 + so, a + (arow0 + row) * (size_t)DM + k0 + c8 * 8);
    }
    #pragma unroll
    for (int it = 0; it < 2; it++) {          // B: 128 rows x 8 chunks, hi+lo
        int c = it * 512 + tid;
        int row = c >> 3, c8 = c & 7;
        uint32_t so = (uint32_t)(row * PA + c8 * 8) * 2;
        size_t gb = (brow0 + row) * (size_t)DM + k0 + c8 * 8;
        CP_ASYNC16(st + G_BHI * 2 + so, b_hi + gb);
        CP_ASYNC16(st + G_BLO * 2 + so, b_lo + gb);
    }
}

__device__ __forceinline__ void gemm_tile_mma(
    const __half* __restrict__ a, size_t arow0,
    const __half* __restrict__ b_hi, const __half* __restrict__ b_lo, size_t brow0,
    float acc[4][4][4])
{
    extern __shared__ __half sm[];
    const int tid = threadIdx.x;
    const int wid = tid >> 5, lane = tid & 31;
    const int mg = (wid & 3) * 64;            // 4 m-groups of 64
    const int ng = (wid >> 2) * 32;           // 4 n-groups of 32

    #pragma unroll
    for (int m = 0; m < 4; m++)
        #pragma unroll
        for (int n = 0; n < 4; n++)
            #pragma unroll
            for (int v = 0; v < 4; v++) acc[m][n][v] = 0.f;

    const uint32_t sb = smem_u32(sm);
    const int a_row_l = (lane & 15);
    const int a_col_l = ((lane >> 4) << 3);
    const int b_row_l = ((lane >> 4) << 3) + (lane & 7);
    const int b_col_l = (((lane >> 3) & 1) << 3);

    g_prefetch(sb, 0, a, arow0, b_hi, b_lo, brow0, 0, tid);
    CP_COMMIT();

    for (int s = 0; s < 16; s++) {
        const int buf = s & 1;
        if (s + 1 < 16) {
            g_prefetch(sb, buf ^ 1, a, arow0, b_hi, b_lo, brow0, (s + 1) * 64, tid);
            CP_COMMIT();
            CP_WAIT(1);
        } else {
            CP_WAIT(0);
        }
        __syncthreads();

        const uint32_t st = sb + (uint32_t)buf * G_STAGE * 2;
        #pragma unroll
        for (int ks = 0; ks < 4; ks++) {
            uint32_t ar[4][4];
            #pragma unroll
            for (int m = 0; m < 4; m++) {
                uint32_t off = (uint32_t)((mg + m * 16 + a_row_l) * PA + ks * 16 + a_col_l) * 2;
                LDSM_X4(ar[m][0], ar[m][1], ar[m][2], ar[m][3], st + G_A * 2 + off);
            }
            #pragma unroll
            for (int p = 0; p < 2; p++) {
                uint32_t off = (uint32_t)((ng + p * 16 + b_row_l) * PA + ks * 16 + b_col_l) * 2;
                uint32_t bh4[4], bl4[4];
                LDSM_X4(bh4[0], bh4[1], bh4[2], bh4[3], st + G_BHI * 2 + off);
                LDSM_X4(bl4[0], bl4[1], bl4[2], bl4[3], st + G_BLO * 2 + off);
                #pragma unroll
                for (int m = 0; m < 4; m++) {
                    mma_fp16(acc[m][2*p],   ar[m], bh4);
                    mma_fp16(acc[m][2*p],   ar[m], bl4);
                    mma_fp16(acc[m][2*p+1], ar[m], bh4 + 2);
                    mma_fp16(acc[m][2*p+1], ar[m], bl4 + 2);
                }
            }
        }
        __syncthreads();
    }
}

// ---------------------------------------------------------------------------
// QKV GEMM: grid (32 mtiles of 256, 24 ntiles of 128).
// ---------------------------------------------------------------------------
__global__ __launch_bounds__(512) void gemm_qkv_tc(
    const float* __restrict__ bq, const float* __restrict__ bk, const float* __restrict__ bv)
{
    const int mt = blockIdx.x, nt = blockIdx.y;
    const size_t arow0 = (size_t)mt * 256;
    const size_t brow0 = (size_t)nt * 128;

    float acc[4][4][4];
    gemm_tile_mma(gx, arow0, gw_hi, gw_lo, brow0, acc);

    const int tid = threadIdx.x, wid = tid >> 5, lane = tid & 31;
    const int mg = (wid & 3) * 64;
    const int gcol0 = nt * 128 + (wid >> 2) * 32;
    const int which = gcol0 >> 10;
    const int h = (gcol0 & 1023) >> 6;
    const float* bias = (which == 0) ? bq : (which == 1) ? bk : bv;

    #pragma unroll
    for (int m = 0; m < 4; m++) {
        #pragma unroll
        for (int n4 = 0; n4 < 4; n4++) {
            #pragma unroll
            for (int half_ = 0; half_ < 2; half_++) {
                int r = mg + m * 16 + (lane >> 2) + half_ * 8;
                int e = (gcol0 & 63) + n4 * 8 + (lane & 3) * 2;
                size_t mrow = arow0 + r;
                int b = (int)(mrow / S), sidx = (int)(mrow % S);
                int bhidx = b * H + h;
                float v0 = acc[m][n4][half_ * 2 + 0] + bias[h * DH + e];
                float v1 = acc[m][n4][half_ * 2 + 1] + bias[h * DH + e + 1];
                if (which == 0) {
                    v0 *= SCALE; v1 *= SCALE;
                    size_t base = ((size_t)bhidx * S + sidx) * DH + e;
                    *(__half2*)&gq[base] = __floats2half2_rn(v0, v1);
                } else if (which == 1) {
                    __half h0, l0, h1, l1;
                    split2h(v0, h0, l0); split2h(v1, h1, l1);
                    size_t base = ((size_t)bhidx * S + sidx) * DH + e;
                    __half2 th; th.x = h0; th.y = h1;
                    __half2 tl; tl.x = l0; tl.y = l1;
                    *(__half2*)&gk_hi[base] = th;
                    *(__half2*)&gk_lo[base] = tl;
                } else {
                    __half h0, l0, h1, l1;
                    split2h(v0, h0, l0); split2h(v1, h1, l1);
                    size_t base = ((size_t)bhidx * DH + e) * S + sidx;
                    gvt_hi[base] = h0;     gvt_lo[base] = l0;
                    gvt_hi[base + S] = h1; gvt_lo[base + S] = l1;
                }
            }
        }
    }
}

// ---------------------------------------------------------------------------
// Output GEMM: grid (32 mtiles of 256, 8 ntiles of 128).
// ---------------------------------------------------------------------------
__global__ __launch_bounds__(512) void gemm_out_tc(const float* __restrict__ bo,
                                                   float* __restrict__ out)
{
    const int mt = blockIdx.x, nt = blockIdx.y;
    const size_t arow0 = (size_t)mt * 256;

    float acc[4][4][4];
    gemm_tile_mma(gh, arow0, gwo_hi, gwo_lo, (size_t)nt * 128, acc);

    const int tid = threadIdx.x, wid = tid >> 5, lane = tid & 31;
    const int mg = (wid & 3) * 64;
    const int gcol0 = nt * 128 + (wid >> 2) * 32;

    #pragma unroll
    for (int m = 0; m < 4; m++) {
        #pragma unroll
        for (int n4 = 0; n4 < 4; n4++) {
            #pragma unroll
            for (int half_ = 0; half_ < 2; half_++) {
                int r = mg + m * 16 + (lane >> 2) + half_ * 8;
                int c = gcol0 + n4 * 8 + (lane & 3) * 2;
                size_t mrow = arow0 + r;
                float2 w = {acc[m][n4][half_ * 2 + 0] + bo[c],
                            acc[m][n4][half_ * 2 + 1] + bo[c + 1]};
                *(float2*)&out[mrow * DM + c] = w;
            }
        }
    }
}

// ---------------------------------------------------------------------------
// Attention (FA2, fp16 2-term both MMAs), cp.async double-buffered KV.
// Unchanged from R7 (validated; reg budget at the 2-CTA/SM boundary).
// ---------------------------------------------------------------------------
#define A_Q 0
#define A_KV0 (128 * PA)
#define A_KV_COMP (64 * PA)
#define A_KV_STAGE (4 * A_KV_COMP)
#define ATT_BYTES ((128 * PA + 2 * A_KV_STAGE) * 2)   // 92160 B

__device__ __forceinline__ void a_prefetch_kv(uint32_t sb, int buf, int bh, int kt, int tid)
{
    uint32_t st = sb + (uint32_t)(A_KV0 + buf * A_KV_STAGE) * 2;
    #pragma unroll
    for (int it = 0; it < 2; it++) {
        int c = it * 256 + tid;
        int row = c >> 3, c8 = c & 7;
        uint32_t so = (uint32_t)(row * PA + c8 * 8) * 2;
        size_t gk = ((size_t)bh * S + kt * 64 + row) * DH + c8 * 8;
        size_t gv = ((size_t)bh * DH + row) * S + kt * 64 + c8 * 8;
        CP_ASYNC16(st + 0 * A_KV_COMP * 2 + so, gk_hi + gk);
        CP_ASYNC16(st + 1 * A_KV_COMP * 2 + so, gk_lo + gk);
        CP_ASYNC16(st + 2 * A_KV_COMP * 2 + so, gvt_hi + gv);
        CP_ASYNC16(st + 3 * A_KV_COMP * 2 + so, gvt_lo + gv);
    }
}

__global__ __launch_bounds__(256) void attn_mma()
{
    extern __shared__ __half sm[];
    const int qt = blockIdx.x;
    const int bh = blockIdx.y;
    const int tid = threadIdx.x, wid = tid >> 5, lane = tid & 31;
    const int base_m = wid * 16;
    const uint32_t sb = smem_u32(sm);
    const int a_row_l = (lane & 15);
    const int a_col_l = ((lane >> 4) << 3);
    const int b_row_l = ((lane >> 4) << 3) + (lane & 7);
    const int b_col_l = (((lane >> 3) & 1) << 3);

    a_prefetch_kv(sb, 0, bh, 0, tid);
    CP_COMMIT();

    const size_t qbase = ((size_t)bh * S + qt * 128) * DH;
    #pragma unroll
    for (int it = 0; it < 4; it++) {
        int c = it * 256 + tid;
        int row = c >> 3, c8 = c & 7;
        *(uint4*)&sm[A_Q + row * PA + c8 * 8] = *(const uint4*)(gq + qbase + (size_t)row * DH + c8 * 8);
    }

    float o[8][4];
    #pragma unroll
    for (int n = 0; n < 8; n++)
        #pragma unroll
        for (int v = 0; v < 4; v++) o[n][v] = 0.f;
    float mrow[2] = {-INFINITY, -INFINITY};
    float lrow[2] = {0.f, 0.f};

    for (int kt = 0; kt < S / 64; kt++) {
        const int buf = kt & 1;
        if (kt + 1 < S / 64) {
            a_prefetch_kv(sb, buf ^ 1, bh, kt + 1, tid);
            CP_COMMIT();
            CP_WAIT(1);
        } else {
            CP_WAIT(0);
        }
        __syncthreads();

        const uint32_t st = sb + (uint32_t)(A_KV0 + buf * A_KV_STAGE) * 2;

        float sc[8][4];
        #pragma unroll
        for (int n = 0; n < 8; n++)
            #pragma unroll
            for (int v = 0; v < 4; v++) sc[n][v] = 0.f;

        #pragma unroll
        for (int ks = 0; ks < 4; ks++) {
            uint32_t ar[4];
            uint32_t aoff = (uint32_t)((base_m + a_row_l) * PA + ks * 16 + a_col_l) * 2;
            LDSM_X4(ar[0], ar[1], ar[2], ar[3], sb + A_Q * 2 + aoff);
            #pragma unroll
            for (int p = 0; p < 4; p++) {
                uint32_t boff = (uint32_t)((p * 16 + b_row_l) * PA + ks * 16 + b_col_l) * 2;
                uint32_t kh4[4], kl4[4];
                LDSM_X4(kh4[0], kh4[1], kh4[2], kh4[3], st + 0 * A_KV_COMP * 2 + boff);
                LDSM_X4(kl4[0], kl4[1], kl4[2], kl4[3], st + 1 * A_KV_COMP * 2 + boff);
                mma_fp16(sc[2*p],   ar, kh4);
                mma_fp16(sc[2*p],   ar, kl4);
                mma_fp16(sc[2*p+1], ar, kh4 + 2);
                mma_fp16(sc[2*p+1], ar, kl4 + 2);
            }
        }

        #pragma unroll
        for (int half_ = 0; half_ < 2; half_++) {
            const int ci = half_ * 2;
            float mx = -INFINITY;
            #pragma unroll
            for (int n = 0; n < 8; n++)
                mx = fmaxf(mx, fmaxf(sc[n][ci], sc[n][ci + 1]));
            mx = fmaxf(mx, __shfl_xor_sync(0xffffffffu, mx, 1));
            mx = fmaxf(mx, __shfl_xor_sync(0xffffffffu, mx, 2));
            float mnew = fmaxf(mrow[half_], mx);
            float f = __expf(mrow[half_] - mnew);
            mrow[half_] = mnew;
            float rs = 0.f;
            #pragma unroll
            for (int n = 0; n < 8; n++) {
                sc[n][ci]     = __expf(sc[n][ci]     - mnew);
                sc[n][ci + 1] = __expf(sc[n][ci + 1] - mnew);
                rs += sc[n][ci] + sc[n][ci + 1];
            }
            rs += __shfl_xor_sync(0xffffffffu, rs, 1);
            rs += __shfl_xor_sync(0xffffffffu, rs, 2);
            lrow[half_] = lrow[half_] * f + rs;
            #pragma unroll
            for (int n = 0; n < 8; n++) {
                o[n][ci] *= f;
                o[n][ci + 1] *= f;
            }
        }

        uint32_t pa[4][4];
        #pragma unroll
        for (int ks = 0; ks < 4; ks++) {
            #pragma unroll
            for (int q = 0; q < 4; q++) {
                int n = 2 * ks + (q >> 1);
                int pr = (q & 1) * 2;
                __half2 t = __floats2half2_rn(sc[n][pr], sc[n][pr + 1]);
                pa[ks][q] = *(uint32_t*)&t;
            }
        }

        #pragma unroll
        for (int ks = 0; ks < 4; ks++) {
            #pragma unroll
            for (int p = 0; p < 4; p++) {
                uint32_t boff = (uint32_t)((p * 16 + b_row_l) * PA + ks * 16 + b_col_l) * 2;
                uint32_t vh4[4], vl4[4];
                LDSM_X4(vh4[0], vh4[1], vh4[2], vh4[3], st + 2 * A_KV_COMP * 2 + boff);
                LDSM_X4(vl4[0], vl4[1], vl4[2], vl4[3], st + 3 * A_KV_COMP * 2 + boff);
                mma_fp16(o[2*p],   pa[ks], vh4);
                mma_fp16(o[2*p],   pa[ks], vl4);
                mma_fp16(o[2*p+1], pa[ks], vh4 + 2);
                mma_fp16(o[2*p+1], pa[ks], vl4 + 2);
            }
        }
        __syncthreads();
    }

    const float inv0 = 1.f / lrow[0];
    const float inv1 = 1.f / lrow[1];
    const int b = bh >> 4, h = bh & 15;
    const int s0 = qt * 128 + base_m + (lane >> 2);
    const size_t tok0 = (size_t)b * S + s0;
    const size_t tok1 = tok0 + 8;
    #pragma unroll
    for (int n = 0; n < 8; n++) {
        int col = h * DH + n * 8 + (lane & 3) * 2;
        *(__half2*)&gh[tok0 * DM + col] = __floats2half2_rn(o[n][0] * inv0, o[n][1] * inv0);
        *(__half2*)&gh[tok1 * DM + col] = __floats2half2_rn(o[n][2] * inv1, o[n][3] * inv1);
    }
}

// ---------------------------------------------------------------------------
extern "C" void kernel_launch(void* const* d_in, const int* in_sizes, int n_in,
                              void* d_out, int out_size)
{
    const float* x  = (const float*)d_in[0];
    const float* Wq = (const float*)d_in[1];
    const float* bq = (const float*)d_in[2];
    const float* Wk = (const float*)d_in[3];
    const float* bk = (const float*)d_in[4];
    const float* Wv = (const float*)d_in[5];
    const float* bv = (const float*)d_in[6];
    const float* Wo = (const float*)d_in[7];
    const float* bo = (const float*)d_in[8];
    float* out = (float*)d_out;

    static bool init = false;
    if (!init) {
        cudaFuncSetAttribute(gemm_qkv_tc, cudaFuncAttributeMaxDynamicSharedMemorySize, GSM_BYTES);
        cudaFuncSetAttribute(gemm_out_tc, cudaFuncAttributeMaxDynamicSharedMemorySize, GSM_BYTES);
        cudaFuncSetAttribute(attn_mma,    cudaFuncAttributeMaxDynamicSharedMemorySize, ATT_BYTES);
        init = true;
    }

    // 1. fused prep (coalesced transpose+split, single launch)
    prep_kernel<<<6144, 256>>>(x, Wq, Wk, Wv, Wo);

    // 2. QKV projection (fp16 2-term HMMA, 256x128 tiles)
    gemm_qkv_tc<<<dim3(32, 24), 512, GSM_BYTES>>>(bq, bk, bv);

    // 3. attention (fp16 2-term HMMA, cp.async pipelined)
    attn_mma<<<dim3(16, 64), 256, ATT_BYTES>>>();

    // 4. output projection (fp16 2-term HMMA, 256x128 tiles)
    gemm_out_tc<<<dim3(32, 8), 512, GSM_BYTES>>>(bo, out);
}